// round 14
// baseline (speedup 1.0000x reference)
#include <cuda_runtime.h>
#include <cuda_bf16.h>
#include <cstdint>

// B=4, T=4096, D=1024, H=8, BUCKETS=64, DH=128, BSZ=64
#define NELEM 16777216

__device__ float g_k[NELEM];
__device__ float g_v[NELEM];
__device__ float g_vre[NELEM];
__device__ float g_R[131072];
// bf16 operands
__device__ __nv_bfloat16 g_qbh[NELEM], g_qbl[NELEM];       // q hi/lo (head-major)
__device__ __nv_bfloat16 g_kbh[NELEM], g_kbl[NELEM];       // k hi/lo (head-major)
__device__ __nv_bfloat16 g_krh[NELEM], g_krl[NELEM];       // k_re hi/lo
__device__ __nv_bfloat16 g_xh[16777216], g_xl[16777216];   // x  [16384][1024]
__device__ __nv_bfloat16 g_ah[16777216], g_al[16777216];   // attn out [16384][1024]
__device__ __nv_bfloat16 g_wqh[3145728], g_wql[3145728];   // w_qkv [3072][1024]
__device__ __nv_bfloat16 g_woh[1048576], g_wol[1048576];   // w_out [1024][1024]

// ---------------- helpers ----------------
__device__ __forceinline__ uint32_t smem_u32(const void* p) {
    uint32_t a;
    asm("{ .reg .u64 t; cvta.to.shared.u64 t, %1; cvt.u32.u64 %0, t; }" : "=r"(a) : "l"(p));
    return a;
}
#define CP16(dst, src) asm volatile("cp.async.cg.shared.global [%0], [%1], 16;" :: "r"(dst), "l"(src))
#define CPCOMMIT()     asm volatile("cp.async.commit_group;" ::: "memory")
#define CPWAIT0()      asm volatile("cp.async.wait_group 0;" ::: "memory")

__device__ __forceinline__ void ldsm4(uint32_t* r, uint32_t a) {
    asm volatile("ldmatrix.sync.aligned.m8n8.x4.shared.b16 {%0,%1,%2,%3}, [%4];"
        : "=r"(r[0]), "=r"(r[1]), "=r"(r[2]), "=r"(r[3]) : "r"(a));
}
__device__ __forceinline__ void mma16816(float* c, const uint32_t* a, const uint32_t* b) {
    asm volatile("mma.sync.aligned.m16n8k16.row.col.f32.bf16.bf16.f32 "
        "{%0,%1,%2,%3}, {%4,%5,%6,%7}, {%8,%9}, {%0,%1,%2,%3};"
        : "+f"(c[0]), "+f"(c[1]), "+f"(c[2]), "+f"(c[3])
        : "r"(a[0]), "r"(a[1]), "r"(a[2]), "r"(a[3]), "r"(b[0]), "r"(b[1]));
}
__device__ __forceinline__ void bf_split(float v, unsigned short& h, unsigned short& l) {
    __nv_bfloat16 hb = __float2bfloat16_rn(v);
    h = __bfloat16_as_ushort(hb);
    l = __bfloat16_as_ushort(__float2bfloat16_rn(v - __bfloat162float(hb)));
}
__device__ __forceinline__ uint32_t pack2h(float a, float b) {
    unsigned short h0, l0, h1, l1;
    bf_split(a, h0, l0); bf_split(b, h1, l1);
    return (uint32_t)h0 | ((uint32_t)h1 << 16);
}
__device__ __forceinline__ uint32_t pack2l(float a, float b) {
    unsigned short h0, l0, h1, l1;
    bf_split(a, h0, l0); bf_split(b, h1, l1);
    return (uint32_t)l0 | ((uint32_t)l1 << 16);
}

// ---------------------------------------------------------------------------
// Prepass: split fp32 -> bf16 hi/lo
// ---------------------------------------------------------------------------
__global__ __launch_bounds__(256)
void split_k(const float4* __restrict__ src, uint2* __restrict__ hi, uint2* __restrict__ lo)
{
    int i = blockIdx.x * 256 + threadIdx.x;
    float4 v = src[i];
    hi[i] = make_uint2(pack2h(v.x, v.y), pack2h(v.z, v.w));
    lo[i] = make_uint2(pack2l(v.x, v.y), pack2l(v.z, v.w));
}

// ---------------------------------------------------------------------------
// bf16x3 tensor GEMM: tile 256x128 (warp tile 64x64), 1 CTA/SM.
// 2-stage cp.async pipeline, ONE __syncthreads per K-chunk (BK=32).
// stage layout (61440B): Ah[256][40] | Al | Bh[128][40] | Bl
// EPI=0: scatter q/k bf16 splits + k/v fp32. EPI=1: C=out + bias.
// ---------------------------------------------------------------------------
template<int EPI>
__global__ __launch_bounds__(256)
void mma_gemm(const __nv_bfloat16* __restrict__ Ah, const __nv_bfloat16* __restrict__ Al,
              const __nv_bfloat16* __restrict__ Bh, const __nv_bfloat16* __restrict__ Bl,
              float* __restrict__ C, const float* __restrict__ bias)
{
    extern __shared__ char sm[];
    const uint32_t sb = smem_u32(sm);
    const int tid = threadIdx.x, lane = tid & 31, wid = tid >> 5;
    const int wm = wid >> 1, wn = wid & 1;           // 4 x 2 warps, 64x64 tiles
    const int m0 = blockIdx.y * 256, n0 = blockIdx.x * 128;
    const int bprow = tid >> 1, bseg0 = (tid & 1) * 2;

    float acc[4][8][4];
#pragma unroll
    for (int i = 0; i < 4; i++)
#pragma unroll
        for (int j = 0; j < 8; j++)
#pragma unroll
            for (int r = 0; r < 4; r++) acc[i][j][r] = 0.f;

    const size_t ga = (size_t)(m0 + tid) * 1024;      // A row = tid (0..255)
    const size_t gb = (size_t)(n0 + bprow) * 1024;

#define ISSUE(c, s) do {                                                        \
    const int k0_ = (c) * 32;                                                   \
    const uint32_t st = sb + (s) * 61440;                                       \
    const uint32_t da = st + tid * 80;                                          \
    _Pragma("unroll")                                                           \
    for (int t = 0; t < 4; t++) {                                               \
        CP16(da + t * 16,         Ah + ga + k0_ + t * 8);                       \
        CP16(da + 20480 + t * 16, Al + ga + k0_ + t * 8);                       \
    }                                                                           \
    const uint32_t db = st + 40960 + bprow * 80;                                \
    _Pragma("unroll")                                                           \
    for (int t = 0; t < 2; t++) {                                               \
        const int sg = bseg0 + t;                                               \
        CP16(db + sg * 16,         Bh + gb + k0_ + sg * 8);                     \
        CP16(db + 10240 + sg * 16, Bl + gb + k0_ + sg * 8);                     \
    }                                                                           \
} while (0)

    ISSUE(0, 0); CPCOMMIT();
#pragma unroll 1
    for (int c = 0; c < 32; c++) {
        CPWAIT0();
        __syncthreads();
        if (c + 1 < 32) { ISSUE(c + 1, (c + 1) & 1); CPCOMMIT(); }
        const uint32_t base = sb + (c & 1) * 61440;
#pragma unroll
        for (int ks = 0; ks < 2; ks++) {
            uint32_t bh[8][2], bl[8][2];
            const int br2 = wn * 64 + (lane & 7) + ((lane >> 4) & 1) * 8;
            const int bc = ks * 16 + ((lane >> 3) & 1) * 8;
#pragma unroll
            for (int jj = 0; jj < 4; jj++) {
                uint32_t ba = base + 40960 + ((br2 + jj * 16) * 40 + bc) * 2;
                uint32_t rb[4];
                ldsm4(rb, ba);
                bh[jj * 2][0] = rb[0]; bh[jj * 2][1] = rb[1];
                bh[jj * 2 + 1][0] = rb[2]; bh[jj * 2 + 1][1] = rb[3];
                ldsm4(rb, ba + 10240);
                bl[jj * 2][0] = rb[0]; bl[jj * 2][1] = rb[1];
                bl[jj * 2 + 1][0] = rb[2]; bl[jj * 2 + 1][1] = rb[3];
            }
            const int ar = wm * 64 + (lane & 7) + ((lane >> 3) & 1) * 8;
            const int ac = ks * 16 + ((lane >> 4) & 1) * 8;
#pragma unroll
            for (int i = 0; i < 4; i++) {
                uint32_t aa = base + ((ar + i * 16) * 40 + ac) * 2;
                uint32_t ah[4], al[4];
                ldsm4(ah, aa);
                ldsm4(al, aa + 20480);
                // product-major order: no back-to-back MMAs on the same accumulator
#pragma unroll
                for (int j = 0; j < 8; j++) mma16816(acc[i][j], ah, bh[j]);
#pragma unroll
                for (int j = 0; j < 8; j++) mma16816(acc[i][j], ah, bl[j]);
#pragma unroll
                for (int j = 0; j < 8; j++) mma16816(acc[i][j], al, bh[j]);
            }
        }
    }

    const int mrow = lane >> 2, ncol = (lane & 3) * 2;
#pragma unroll
    for (int i = 0; i < 4; i++) {
#pragma unroll
        for (int j = 0; j < 8; j++) {
            const int gm = m0 + wm * 64 + i * 16 + mrow;
            const int gn = n0 + wn * 64 + j * 8 + ncol;
            if (EPI == 0) {
                const int slice = n0 >> 10, h = (n0 >> 7) & 7;
                const int nn = gn & 127;
                size_t e0 = ((size_t)((gm >> 12) * 8 + h) * 4096 + (gm & 4095)) * 128 + nn;
                size_t e1 = ((size_t)(((gm + 8) >> 12) * 8 + h) * 4096 + ((gm + 8) & 4095)) * 128 + nn;
                float c0 = acc[i][j][0], c1 = acc[i][j][1], c2 = acc[i][j][2], c3 = acc[i][j][3];
                if (slice == 0) {            // q: bf16 hi/lo only
                    *(uint32_t*)(g_qbh + e0) = pack2h(c0, c1);
                    *(uint32_t*)(g_qbl + e0) = pack2l(c0, c1);
                    *(uint32_t*)(g_qbh + e1) = pack2h(c2, c3);
                    *(uint32_t*)(g_qbl + e1) = pack2l(c2, c3);
                } else if (slice == 1) {     // k: fp32 + bf16 hi/lo
                    *(float2*)(g_k + e0) = make_float2(c0, c1);
                    *(float2*)(g_k + e1) = make_float2(c2, c3);
                    *(uint32_t*)(g_kbh + e0) = pack2h(c0, c1);
                    *(uint32_t*)(g_kbl + e0) = pack2l(c0, c1);
                    *(uint32_t*)(g_kbh + e1) = pack2h(c2, c3);
                    *(uint32_t*)(g_kbl + e1) = pack2l(c2, c3);
                } else {                     // v: fp32
                    *(float2*)(g_v + e0) = make_float2(c0, c1);
                    *(float2*)(g_v + e1) = make_float2(c2, c3);
                }
            } else {
                float2 bv = *(const float2*)(bias + gn);
                *(float2*)(C + (size_t)gm * 1024 + gn) =
                    make_float2(acc[i][j][0] + bv.x, acc[i][j][1] + bv.y);
                *(float2*)(C + (size_t)(gm + 8) * 1024 + gn) =
                    make_float2(acc[i][j][2] + bv.x, acc[i][j][3] + bv.y);
            }
        }
    }
}

// ---------------------------------------------------------------------------
// Sinkhorn sorting matrix (reads fp32 g_k)
// ---------------------------------------------------------------------------
__global__ __launch_bounds__(256)
void sinkhorn_k(const float* __restrict__ sort_w, const float* __restrict__ noise_u)
{
    __shared__ float sh[8192];
    const int bh = blockIdx.x, h = bh & 7, tid = threadIdx.x;
#pragma unroll 1
    for (int c = 0; c < 32; c++) {
        int idx = tid + c * 256;
        int uu = idx >> 7, dd = idx & 127;
        const float* kp = g_k + ((size_t)bh * 4096 + uu * 64) * 128 + dd;
        float s = 0.f;
#pragma unroll 8
        for (int i = 0; i < 64; i++) s += kp[(size_t)i * 128];
        sh[idx] = s;
    }
    __syncthreads();
    float logit[16];
#pragma unroll 1
    for (int c = 0; c < 16; c++) {
        int idx = tid + c * 256;
        int uu = idx >> 6, vv = idx & 63;
        const float* wp = sort_w + h * 8192 + vv;
        const float* bp = sh + uu * 128;
        float s = 0.f;
#pragma unroll 8
        for (int d = 0; d < 128; d++) s += bp[d] * wp[d * 64];
        float nu = noise_u[(size_t)bh * 4096 + idx];
        float g = -logf(-logf(nu + 1e-4f) + 1e-4f);
        logit[c] = (logf(fmaxf(s, 0.f) + 1e-6f) + g) * (1.0f / 0.75f);
    }
    __syncthreads();
#pragma unroll
    for (int c = 0; c < 16; c++) sh[tid + c * 256] = logit[c];
    __syncthreads();
    for (int it = 0; it < 5; it++) {
        if (tid < 64) {
            float m = -1e30f;
            for (int v = 0; v < 64; v++) m = fmaxf(m, sh[tid * 64 + ((v + tid) & 63)]);
            float s = 0.f;
            for (int v = 0; v < 64; v++) s += expf(sh[tid * 64 + ((v + tid) & 63)] - m);
            float l = m + logf(s);
            for (int v = 0; v < 64; v++) sh[tid * 64 + ((v + tid) & 63)] -= l;
        }
        __syncthreads();
        if (tid < 64) {
            float m = -1e30f;
            for (int u = 0; u < 64; u++) m = fmaxf(m, sh[u * 64 + tid]);
            float s = 0.f;
            for (int u = 0; u < 64; u++) s += expf(sh[u * 64 + tid] - m);
            float l = m + logf(s);
            for (int u = 0; u < 64; u++) sh[u * 64 + tid] -= l;
        }
        __syncthreads();
    }
#pragma unroll
    for (int c = 0; c < 16; c++) {
        int idx = tid + c * 256;
        int uu = idx >> 6, vv = idx & 63;
        g_R[(size_t)bh * 4096 + idx] = (vv < uu) ? expf(sh[idx]) : 0.f;
    }
}

// ---------------------------------------------------------------------------
// k_re/v_re soft permute, u-tiled. arr==0 -> k_re bf16 hi/lo; arr==1 -> vre fp32.
// ---------------------------------------------------------------------------
__global__ __launch_bounds__(256)
void permute_tiled_k(void)
{
    const int arr = blockIdx.x >> 1, half = blockIdx.x & 1;
    const int u0 = blockIdx.y * 8, bh = blockIdx.z;
    const int tid = threadIdx.x;

    __shared__ float rr[512];
    for (int i = tid; i < 512; i += 256)
        rr[i] = g_R[(size_t)bh * 4096 + (u0 + (i >> 6)) * 64 + (i & 63)];
    __syncthreads();

    const float4* src = (const float4*)(arr == 0 ? g_k : g_v) + (size_t)bh * 131072 + half * 1024 + tid;
    const size_t dbase = (size_t)(bh * 64 + u0) * 2048 + half * 1024 + tid;

    float4 acc[8][4];
#pragma unroll
    for (int t = 0; t < 8; t++)
#pragma unroll
        for (int j = 0; j < 4; j++) acc[t][j] = make_float4(0.f, 0.f, 0.f, 0.f);

    const int vmax = u0 + 7;
#pragma unroll 1
    for (int vv = 0; vv < vmax; vv++) {
        float4 d[4];
#pragma unroll
        for (int j = 0; j < 4; j++) d[j] = src[(size_t)vv * 2048 + j * 256];
#pragma unroll
        for (int t = 0; t < 8; t++) {
            float r = rr[t * 64 + vv];
#pragma unroll
            for (int j = 0; j < 4; j++) {
                acc[t][j].x += r * d[j].x; acc[t][j].y += r * d[j].y;
                acc[t][j].z += r * d[j].z; acc[t][j].w += r * d[j].w;
            }
        }
    }
    if (arr == 0) {
        uint2* dh = (uint2*)g_krh + dbase;
        uint2* dl = (uint2*)g_krl + dbase;
#pragma unroll
        for (int t = 0; t < 8; t++)
#pragma unroll
            for (int j = 0; j < 4; j++) {
                float4 a = acc[t][j];
                dh[(size_t)t * 2048 + j * 256] = make_uint2(pack2h(a.x, a.y), pack2h(a.z, a.w));
                dl[(size_t)t * 2048 + j * 256] = make_uint2(pack2l(a.x, a.y), pack2l(a.z, a.w));
            }
    } else {
        float4* dst = (float4*)g_vre + dbase;
#pragma unroll
        for (int t = 0; t < 8; t++)
#pragma unroll
            for (int j = 0; j < 4; j++)
                dst[(size_t)t * 2048 + j * 256] = acc[t][j];
    }
}

// ---------------------------------------------------------------------------
// Bucketed attention: tensorized dots (bf16x3 mma), fp32 softmax + out.
// smem bytes: qh 0..17408 | ql ..34816 | k2h ..69632 | k2l ..104448
// sd (64x130 f32) overlays q region after dots; v2 fp32 overlays k2 region.
// Total smem = 104448 B. (unchanged from passing R13)
// ---------------------------------------------------------------------------
#define OFF_QH  0
#define OFF_QL  17408
#define OFF_K2H 34816
#define OFF_K2L 69632
#define ATTN_SMEM 104448

__global__ __launch_bounds__(256)
void attn_k(void)
{
    extern __shared__ float smf[];
    char* smc = (char*)smf;
    const uint32_t sb = smem_u32(smf);
    float* sd = smf;                     // overlays q region after dots
    float* skv = smf + OFF_K2H / 4;      // v2 overlay (fp32, stride 128)
    const int u = blockIdx.x, bh = blockIdx.y, tid = threadIdx.x;
    const size_t boff = ((size_t)bh * 4096 + u * 64) * 128;
    const size_t reoff = ((size_t)bh * 64 + u) * 8192;

    {
        const uint4* qh = (const uint4*)g_qbh + (boff >> 3);
        const uint4* ql = (const uint4*)g_qbl + (boff >> 3);
#pragma unroll
        for (int c = 0; c < 4; c++) {
            int idx = tid + c * 256;
            uint32_t so = (idx >> 4) * 272 + (idx & 15) * 16;
            *(uint4*)(smc + OFF_QH + so) = qh[idx];
            *(uint4*)(smc + OFF_QL + so) = ql[idx];
        }
        const uint4* krh = (const uint4*)g_krh + (reoff >> 3);
        const uint4* krl = (const uint4*)g_krl + (reoff >> 3);
        const uint4* kbh = (const uint4*)g_kbh + (boff >> 3);
        const uint4* kbl = (const uint4*)g_kbl + (boff >> 3);
#pragma unroll
        for (int c = 0; c < 8; c++) {
            int idx = tid + c * 256;
            int r = idx >> 4;
            uint32_t so = r * 272 + (idx & 15) * 16;
            *(uint4*)(smc + OFF_K2H + so) = (r < 64) ? krh[idx] : kbh[idx - 1024];
            *(uint4*)(smc + OFF_K2L + so) = (r < 64) ? krl[idx] : kbl[idx - 1024];
        }
    }
    __syncthreads();

    {
        const int lane = tid & 31, wid = tid >> 5;
        const int wm = wid >> 2, wn = wid & 3;
        const int arow = (lane & 7) + ((lane >> 3) & 1) * 8;
        const int acol = ((lane >> 4) & 1) * 8;
        const int brow = (lane & 7) + ((lane >> 4) & 1) * 8;
        const int bcol = ((lane >> 3) & 1) * 8;
        float acc[2][4][4];
#pragma unroll
        for (int i = 0; i < 2; i++)
#pragma unroll
            for (int j = 0; j < 4; j++)
#pragma unroll
                for (int r = 0; r < 4; r++) acc[i][j][r] = 0.f;

#pragma unroll
        for (int kc = 0; kc < 8; kc++) {
            uint32_t bh[4][2], bl[4][2];
#pragma unroll
            for (int jj = 0; jj < 2; jj++) {
                uint32_t ba = sb + OFF_K2H + ((wn * 32 + jj * 16 + brow) * 136 + kc * 16 + bcol) * 2;
                uint32_t rb[4];
                ldsm4(rb, ba);
                bh[jj * 2][0] = rb[0]; bh[jj * 2][1] = rb[1];
                bh[jj * 2 + 1][0] = rb[2]; bh[jj * 2 + 1][1] = rb[3];
                ldsm4(rb, ba + (OFF_K2L - OFF_K2H));
                bl[jj * 2][0] = rb[0]; bl[jj * 2][1] = rb[1];
                bl[jj * 2 + 1][0] = rb[2]; bl[jj * 2 + 1][1] = rb[3];
            }
#pragma unroll
            for (int i = 0; i < 2; i++) {
                uint32_t aa = sb + OFF_QH + ((wm * 32 + i * 16 + arow) * 136 + kc * 16 + acol) * 2;
                uint32_t ah[4], al[4];
                ldsm4(ah, aa);
                ldsm4(al, aa + (OFF_QL - OFF_QH));
#pragma unroll
                for (int j = 0; j < 4; j++) mma16816(acc[i][j], ah, bh[j]);
#pragma unroll
                for (int j = 0; j < 4; j++) mma16816(acc[i][j], ah, bl[j]);
#pragma unroll
                for (int j = 0; j < 4; j++) mma16816(acc[i][j], al, bh[j]);
            }
        }
        __syncthreads();   // all q reads complete before sd overlays the q region
        const float sc = 0.03125f;     // 1024^-0.5
#pragma unroll
        for (int i = 0; i < 2; i++)
#pragma unroll
            for (int j = 0; j < 4; j++) {
                int row = wm * 32 + i * 16 + (lane >> 2);
                int col = wn * 32 + j * 8 + (lane & 3) * 2;
                *(float2*)&sd[row * 130 + col] = make_float2(acc[i][j][0] * sc, acc[i][j][1] * sc);
                *(float2*)&sd[(row + 8) * 130 + col] = make_float2(acc[i][j][2] * sc, acc[i][j][3] * sc);
            }
    }
    __syncthreads();

    {
        const int row = tid >> 2;
        float* rp = sd + row * 130 + (tid & 3) * 32;
        float m = -1e30f;
#pragma unroll
        for (int j = 0; j < 32; j++) m = fmaxf(m, rp[(j + tid) & 31]);
        m = fmaxf(m, __shfl_xor_sync(0xffffffffu, m, 1, 4));
        m = fmaxf(m, __shfl_xor_sync(0xffffffffu, m, 2, 4));
        float s = 0.f;
#pragma unroll
        for (int j = 0; j < 32; j++) {
            int jj = (j + tid) & 31;
            float e = __expf(rp[jj] - m);
            rp[jj] = e;
            s += e;
        }
        s += __shfl_xor_sync(0xffffffffu, s, 1, 4);
        s += __shfl_xor_sync(0xffffffffu, s, 2, 4);
        float inv = 1.f / s;
#pragma unroll
        for (int j = 0; j < 32; j++) { int jj = (j + tid) & 31; rp[jj] *= inv; }

        float4* skv4 = (float4*)skv;
        const float4* vre = (const float4*)(g_vre + reoff);
        const float4* vg = (const float4*)(g_v + boff);
#pragma unroll
        for (int c = 0; c < 8; c++) {
            int idx = tid + c * 256;
            skv4[idx] = vre[idx];
            skv4[idx + 2048] = vg[idx];
        }
    }
    __syncthreads();

    {
        const int ti = (tid >> 4) * 4, te = (tid & 15) * 8;
        float acc[4][8];
#pragma unroll
        for (int ii = 0; ii < 4; ii++)
#pragma unroll
            for (int jj = 0; jj < 8; jj++) acc[ii][jj] = 0.f;
        for (int j = 0; j < 128; j++) {
            float a[4];
#pragma unroll
            for (int ii = 0; ii < 4; ii++) a[ii] = sd[(ti + ii) * 130 + j];
            float4 b0 = *(const float4*)&skv[j * 128 + te];
            float4 b1 = *(const float4*)&skv[j * 128 + te + 4];
#pragma unroll
            for (int ii = 0; ii < 4; ii++) {
                acc[ii][0] += a[ii] * b0.x; acc[ii][1] += a[ii] * b0.y;
                acc[ii][2] += a[ii] * b0.z; acc[ii][3] += a[ii] * b0.w;
                acc[ii][4] += a[ii] * b1.x; acc[ii][5] += a[ii] * b1.y;
                acc[ii][6] += a[ii] * b1.z; acc[ii][7] += a[ii] * b1.w;
            }
        }
        const int bb = bh >> 3, hh = bh & 7;
#pragma unroll
        for (int ii = 0; ii < 4; ii++) {
            size_t base = (size_t)(bb * 4096 + u * 64 + ti + ii) * 1024 + hh * 128 + te;
            uint4 hv = make_uint4(pack2h(acc[ii][0], acc[ii][1]), pack2h(acc[ii][2], acc[ii][3]),
                                  pack2h(acc[ii][4], acc[ii][5]), pack2h(acc[ii][6], acc[ii][7]));
            uint4 lv = make_uint4(pack2l(acc[ii][0], acc[ii][1]), pack2l(acc[ii][2], acc[ii][3]),
                                  pack2l(acc[ii][4], acc[ii][5]), pack2l(acc[ii][6], acc[ii][7]));
            *(uint4*)(g_ah + base) = hv;
            *(uint4*)(g_al + base) = lv;
        }
    }
}

// ---------------------------------------------------------------------------
extern "C" void kernel_launch(void* const* d_in, const int* in_sizes, int n_in,
                              void* d_out, int out_size)
{
    const float* x       = (const float*)d_in[0];
    const float* w_qkv   = (const float*)d_in[1];
    const float* sort_w  = (const float*)d_in[2];
    const float* w_out   = (const float*)d_in[3];
    const float* b_out   = (const float*)d_in[4];
    const float* noise_u = (const float*)d_in[5];
    float* out = (float*)d_out;

    __nv_bfloat16 *xh, *xl, *wqh, *wql, *woh, *wol, *ah, *al;
    cudaGetSymbolAddress((void**)&xh,  g_xh);  cudaGetSymbolAddress((void**)&xl,  g_xl);
    cudaGetSymbolAddress((void**)&wqh, g_wqh); cudaGetSymbolAddress((void**)&wql, g_wql);
    cudaGetSymbolAddress((void**)&woh, g_woh); cudaGetSymbolAddress((void**)&wol, g_wol);
    cudaGetSymbolAddress((void**)&ah,  g_ah);  cudaGetSymbolAddress((void**)&al,  g_al);

    (void)cudaFuncSetAttribute(attn_k, cudaFuncAttributeMaxDynamicSharedMemorySize, ATTN_SMEM);
    (void)cudaFuncSetAttribute(mma_gemm<0>, cudaFuncAttributeMaxDynamicSharedMemorySize, 122880);
    (void)cudaFuncSetAttribute(mma_gemm<1>, cudaFuncAttributeMaxDynamicSharedMemorySize, 122880);

    // prepass: bf16 hi/lo splits
    split_k<<<16384, 256>>>((const float4*)x, (uint2*)xh, (uint2*)xl);
    split_k<<<3072, 256>>>((const float4*)w_qkv, (uint2*)wqh, (uint2*)wql);
    split_k<<<1024, 256>>>((const float4*)w_out, (uint2*)woh, (uint2*)wol);

    // 1) qkv = x @ w_qkv^T  (tensor bf16x3), q/k bf16 splits + k/v fp32
    mma_gemm<0><<<dim3(24, 64), 256, 122880>>>(xh, xl, wqh, wql, nullptr, nullptr);
    // 2) sinkhorn R
    sinkhorn_k<<<32, 256>>>(sort_w, noise_u);
    // 3) k_re (bf16 split) / v_re (fp32), u-tiled
    permute_tiled_k<<<dim3(4, 8, 32), 256>>>();
    // 4) bucketed attention (tensor dots) -> g_ah/g_al
    attn_k<<<dim3(64, 32), 256, ATTN_SMEM>>>();
    // 5) out = attn @ w_out^T + b_out  (tensor bf16x3)
    mma_gemm<1><<<dim3(8, 64), 256, 122880>>>(ah, al, woh, wol, out, b_out);
}

// round 15
// speedup vs baseline: 1.1678x; 1.1678x over previous
#include <cuda_runtime.h>
#include <cuda_bf16.h>
#include <cstdint>

// B=4, T=4096, D=1024, H=8, BUCKETS=64, DH=128, BSZ=64
#define NELEM 16777216

__device__ float g_k[NELEM];
__device__ float g_v[NELEM];
__device__ float g_vre[NELEM];
__device__ float g_R[131072];
// bf16 operands
__device__ __nv_bfloat16 g_qbh[NELEM], g_qbl[NELEM];       // q hi/lo (head-major)
__device__ __nv_bfloat16 g_kbh[NELEM], g_kbl[NELEM];       // k hi/lo (head-major)
__device__ __nv_bfloat16 g_krh[NELEM], g_krl[NELEM];       // k_re hi/lo
__device__ __nv_bfloat16 g_xh[16777216], g_xl[16777216];   // x  [16384][1024]
__device__ __nv_bfloat16 g_ah[16777216], g_al[16777216];   // attn out [16384][1024]
__device__ __nv_bfloat16 g_wqh[3145728], g_wql[3145728];   // w_qkv [3072][1024]
__device__ __nv_bfloat16 g_woh[1048576], g_wol[1048576];   // w_out [1024][1024]

// ---------------- helpers ----------------
__device__ __forceinline__ uint32_t smem_u32(const void* p) {
    uint32_t a;
    asm("{ .reg .u64 t; cvta.to.shared.u64 t, %1; cvt.u32.u64 %0, t; }" : "=r"(a) : "l"(p));
    return a;
}
#define CP16(dst, src) asm volatile("cp.async.cg.shared.global [%0], [%1], 16;" :: "r"(dst), "l"(src))
#define CPCOMMIT()     asm volatile("cp.async.commit_group;" ::: "memory")
#define CPWAIT0()      asm volatile("cp.async.wait_group 0;" ::: "memory")

__device__ __forceinline__ void ldsm4(uint32_t* r, uint32_t a) {
    asm volatile("ldmatrix.sync.aligned.m8n8.x4.shared.b16 {%0,%1,%2,%3}, [%4];"
        : "=r"(r[0]), "=r"(r[1]), "=r"(r[2]), "=r"(r[3]) : "r"(a));
}
__device__ __forceinline__ void mma16816(float* c, const uint32_t* a, const uint32_t* b) {
    asm volatile("mma.sync.aligned.m16n8k16.row.col.f32.bf16.bf16.f32 "
        "{%0,%1,%2,%3}, {%4,%5,%6,%7}, {%8,%9}, {%0,%1,%2,%3};"
        : "+f"(c[0]), "+f"(c[1]), "+f"(c[2]), "+f"(c[3])
        : "r"(a[0]), "r"(a[1]), "r"(a[2]), "r"(a[3]), "r"(b[0]), "r"(b[1]));
}
__device__ __forceinline__ void bf_split(float v, unsigned short& h, unsigned short& l) {
    __nv_bfloat16 hb = __float2bfloat16_rn(v);
    h = __bfloat16_as_ushort(hb);
    l = __bfloat16_as_ushort(__float2bfloat16_rn(v - __bfloat162float(hb)));
}
__device__ __forceinline__ uint32_t pack2h(float a, float b) {
    unsigned short h0, l0, h1, l1;
    bf_split(a, h0, l0); bf_split(b, h1, l1);
    return (uint32_t)h0 | ((uint32_t)h1 << 16);
}
__device__ __forceinline__ uint32_t pack2l(float a, float b) {
    unsigned short h0, l0, h1, l1;
    bf_split(a, h0, l0); bf_split(b, h1, l1);
    return (uint32_t)l0 | ((uint32_t)l1 << 16);
}

// ---------------------------------------------------------------------------
// Prepass: split fp32 -> bf16 hi/lo
// ---------------------------------------------------------------------------
__global__ __launch_bounds__(256)
void split_k(const float4* __restrict__ src, uint2* __restrict__ hi, uint2* __restrict__ lo)
{
    int i = blockIdx.x * 256 + threadIdx.x;
    float4 v = src[i];
    hi[i] = make_uint2(pack2h(v.x, v.y), pack2h(v.z, v.w));
    lo[i] = make_uint2(pack2l(v.x, v.y), pack2l(v.z, v.w));
}

// ---------------------------------------------------------------------------
// bf16x3 tensor GEMM: tile 128x128, 2-stage cp.async, ONE sync per chunk,
// 80KB smem -> 2 CTAs/SM (proven best config, R13). Product-major MMA order.
// EPI=0: scatter q/k bf16 splits + k/v fp32. EPI=1: C=out + bias.
// ---------------------------------------------------------------------------
template<int EPI>
__global__ __launch_bounds__(256)
void mma_gemm(const __nv_bfloat16* __restrict__ Ah, const __nv_bfloat16* __restrict__ Al,
              const __nv_bfloat16* __restrict__ Bh, const __nv_bfloat16* __restrict__ Bl,
              float* __restrict__ C, const float* __restrict__ bias)
{
    extern __shared__ char sm[];
    const uint32_t sb = smem_u32(sm);
    const int tid = threadIdx.x, lane = tid & 31, wid = tid >> 5;
    const int wm = wid >> 2, wn = wid & 3;
    const int m0 = blockIdx.y * 128, n0 = blockIdx.x * 128;
    const int prow = tid >> 1, pseg0 = (tid & 1) * 2;

    float acc[4][4][4];
#pragma unroll
    for (int i = 0; i < 4; i++)
#pragma unroll
        for (int j = 0; j < 4; j++)
#pragma unroll
            for (int r = 0; r < 4; r++) acc[i][j][r] = 0.f;

    const size_t arow = (size_t)(m0 + prow) * 1024;
    const size_t brow = (size_t)(n0 + prow) * 1024;

#define ISSUE(c, s) do {                                                        \
    const int k0_ = (c) * 32;                                                   \
    const uint32_t db = sb + (s) * 40960 + prow * 80;                           \
    _Pragma("unroll")                                                           \
    for (int t = 0; t < 2; t++) {                                               \
        const int sg = pseg0 + t;                                               \
        const uint32_t d0 = db + sg * 16;                                       \
        const size_t go = k0_ + sg * 8;                                         \
        CP16(d0,         Ah + arow + go);                                       \
        CP16(d0 + 10240, Al + arow + go);                                       \
        CP16(d0 + 20480, Bh + brow + go);                                       \
        CP16(d0 + 30720, Bl + brow + go);                                       \
    }                                                                           \
} while (0)

    ISSUE(0, 0); CPCOMMIT();
#pragma unroll 1
    for (int c = 0; c < 32; c++) {
        CPWAIT0();
        __syncthreads();
        if (c + 1 < 32) { ISSUE(c + 1, (c + 1) & 1); CPCOMMIT(); }
        const uint32_t base = sb + (c & 1) * 40960;
#pragma unroll
        for (int ks = 0; ks < 2; ks++) {
            uint32_t bh[4][2], bl[4][2];
            const int br2 = wn * 32 + (lane & 7) + ((lane >> 4) & 1) * 8;
            const int bc = ks * 16 + ((lane >> 3) & 1) * 8;
#pragma unroll
            for (int jj = 0; jj < 2; jj++) {
                uint32_t ba = base + 20480 + ((br2 + jj * 16) * 40 + bc) * 2;
                uint32_t rb[4];
                ldsm4(rb, ba);
                bh[jj * 2][0] = rb[0]; bh[jj * 2][1] = rb[1];
                bh[jj * 2 + 1][0] = rb[2]; bh[jj * 2 + 1][1] = rb[3];
                ldsm4(rb, ba + 10240);
                bl[jj * 2][0] = rb[0]; bl[jj * 2][1] = rb[1];
                bl[jj * 2 + 1][0] = rb[2]; bl[jj * 2 + 1][1] = rb[3];
            }
            const int ar = wm * 64 + (lane & 7) + ((lane >> 3) & 1) * 8;
            const int ac = ks * 16 + ((lane >> 4) & 1) * 8;
#pragma unroll
            for (int i = 0; i < 4; i++) {
                uint32_t aa = base + ((ar + i * 16) * 40 + ac) * 2;
                uint32_t ah[4], al[4];
                ldsm4(ah, aa);
                ldsm4(al, aa + 10240);
                // product-major: no back-to-back MMAs on the same accumulator
#pragma unroll
                for (int j = 0; j < 4; j++) mma16816(acc[i][j], ah, bh[j]);
#pragma unroll
                for (int j = 0; j < 4; j++) mma16816(acc[i][j], ah, bl[j]);
#pragma unroll
                for (int j = 0; j < 4; j++) mma16816(acc[i][j], al, bh[j]);
            }
        }
    }

    const int mrow = lane >> 2, ncol = (lane & 3) * 2;
#pragma unroll
    for (int i = 0; i < 4; i++) {
#pragma unroll
        for (int j = 0; j < 4; j++) {
            const int gm = m0 + wm * 64 + i * 16 + mrow;
            const int gn = n0 + wn * 32 + j * 8 + ncol;
            if (EPI == 0) {
                const int slice = n0 >> 10, h = (n0 >> 7) & 7;
                const int nn = gn & 127;
                size_t e0 = ((size_t)((gm >> 12) * 8 + h) * 4096 + (gm & 4095)) * 128 + nn;
                size_t e1 = ((size_t)(((gm + 8) >> 12) * 8 + h) * 4096 + ((gm + 8) & 4095)) * 128 + nn;
                float c0 = acc[i][j][0], c1 = acc[i][j][1], c2 = acc[i][j][2], c3 = acc[i][j][3];
                if (slice == 0) {            // q: bf16 hi/lo only
                    *(uint32_t*)(g_qbh + e0) = pack2h(c0, c1);
                    *(uint32_t*)(g_qbl + e0) = pack2l(c0, c1);
                    *(uint32_t*)(g_qbh + e1) = pack2h(c2, c3);
                    *(uint32_t*)(g_qbl + e1) = pack2l(c2, c3);
                } else if (slice == 1) {     // k: fp32 + bf16 hi/lo
                    *(float2*)(g_k + e0) = make_float2(c0, c1);
                    *(float2*)(g_k + e1) = make_float2(c2, c3);
                    *(uint32_t*)(g_kbh + e0) = pack2h(c0, c1);
                    *(uint32_t*)(g_kbl + e0) = pack2l(c0, c1);
                    *(uint32_t*)(g_kbh + e1) = pack2h(c2, c3);
                    *(uint32_t*)(g_kbl + e1) = pack2l(c2, c3);
                } else {                     // v: fp32
                    *(float2*)(g_v + e0) = make_float2(c0, c1);
                    *(float2*)(g_v + e1) = make_float2(c2, c3);
                }
            } else {
                float2 bv = *(const float2*)(bias + gn);
                *(float2*)(C + (size_t)gm * 1024 + gn) =
                    make_float2(acc[i][j][0] + bv.x, acc[i][j][1] + bv.y);
                *(float2*)(C + (size_t)(gm + 8) * 1024 + gn) =
                    make_float2(acc[i][j][2] + bv.x, acc[i][j][3] + bv.y);
            }
        }
    }
}

// ---------------------------------------------------------------------------
// Sinkhorn sorting matrix (reads fp32 g_k)
// ---------------------------------------------------------------------------
__global__ __launch_bounds__(256)
void sinkhorn_k(const float* __restrict__ sort_w, const float* __restrict__ noise_u)
{
    __shared__ float sh[8192];
    const int bh = blockIdx.x, h = bh & 7, tid = threadIdx.x;
#pragma unroll 1
    for (int c = 0; c < 32; c++) {
        int idx = tid + c * 256;
        int uu = idx >> 7, dd = idx & 127;
        const float* kp = g_k + ((size_t)bh * 4096 + uu * 64) * 128 + dd;
        float s = 0.f;
#pragma unroll 8
        for (int i = 0; i < 64; i++) s += kp[(size_t)i * 128];
        sh[idx] = s;
    }
    __syncthreads();
    float logit[16];
#pragma unroll 1
    for (int c = 0; c < 16; c++) {
        int idx = tid + c * 256;
        int uu = idx >> 6, vv = idx & 63;
        const float* wp = sort_w + h * 8192 + vv;
        const float* bp = sh + uu * 128;
        float s = 0.f;
#pragma unroll 8
        for (int d = 0; d < 128; d++) s += bp[d] * wp[d * 64];
        float nu = noise_u[(size_t)bh * 4096 + idx];
        float g = -logf(-logf(nu + 1e-4f) + 1e-4f);
        logit[c] = (logf(fmaxf(s, 0.f) + 1e-6f) + g) * (1.0f / 0.75f);
    }
    __syncthreads();
#pragma unroll
    for (int c = 0; c < 16; c++) sh[tid + c * 256] = logit[c];
    __syncthreads();
    for (int it = 0; it < 5; it++) {
        if (tid < 64) {
            float m = -1e30f;
            for (int v = 0; v < 64; v++) m = fmaxf(m, sh[tid * 64 + ((v + tid) & 63)]);
            float s = 0.f;
            for (int v = 0; v < 64; v++) s += expf(sh[tid * 64 + ((v + tid) & 63)] - m);
            float l = m + logf(s);
            for (int v = 0; v < 64; v++) sh[tid * 64 + ((v + tid) & 63)] -= l;
        }
        __syncthreads();
        if (tid < 64) {
            float m = -1e30f;
            for (int u = 0; u < 64; u++) m = fmaxf(m, sh[u * 64 + tid]);
            float s = 0.f;
            for (int u = 0; u < 64; u++) s += expf(sh[u * 64 + tid] - m);
            float l = m + logf(s);
            for (int u = 0; u < 64; u++) sh[u * 64 + tid] -= l;
        }
        __syncthreads();
    }
#pragma unroll
    for (int c = 0; c < 16; c++) {
        int idx = tid + c * 256;
        int uu = idx >> 6, vv = idx & 63;
        g_R[(size_t)bh * 4096 + idx] = (vv < uu) ? expf(sh[idx]) : 0.f;
    }
}

// ---------------------------------------------------------------------------
// k_re/v_re soft permute, u-tiled. arr==0 -> k_re bf16 hi/lo; arr==1 -> vre fp32.
// ---------------------------------------------------------------------------
__global__ __launch_bounds__(256)
void permute_tiled_k(void)
{
    const int arr = blockIdx.x >> 1, half = blockIdx.x & 1;
    const int u0 = blockIdx.y * 8, bh = blockIdx.z;
    const int tid = threadIdx.x;

    __shared__ float rr[512];
    for (int i = tid; i < 512; i += 256)
        rr[i] = g_R[(size_t)bh * 4096 + (u0 + (i >> 6)) * 64 + (i & 63)];
    __syncthreads();

    const float4* src = (const float4*)(arr == 0 ? g_k : g_v) + (size_t)bh * 131072 + half * 1024 + tid;
    const size_t dbase = (size_t)(bh * 64 + u0) * 2048 + half * 1024 + tid;

    float4 acc[8][4];
#pragma unroll
    for (int t = 0; t < 8; t++)
#pragma unroll
        for (int j = 0; j < 4; j++) acc[t][j] = make_float4(0.f, 0.f, 0.f, 0.f);

    const int vmax = u0 + 7;
#pragma unroll 1
    for (int vv = 0; vv < vmax; vv++) {
        float4 d[4];
#pragma unroll
        for (int j = 0; j < 4; j++) d[j] = src[(size_t)vv * 2048 + j * 256];
#pragma unroll
        for (int t = 0; t < 8; t++) {
            float r = rr[t * 64 + vv];
#pragma unroll
            for (int j = 0; j < 4; j++) {
                acc[t][j].x += r * d[j].x; acc[t][j].y += r * d[j].y;
                acc[t][j].z += r * d[j].z; acc[t][j].w += r * d[j].w;
            }
        }
    }
    if (arr == 0) {
        uint2* dh = (uint2*)g_krh + dbase;
        uint2* dl = (uint2*)g_krl + dbase;
#pragma unroll
        for (int t = 0; t < 8; t++)
#pragma unroll
            for (int j = 0; j < 4; j++) {
                float4 a = acc[t][j];
                dh[(size_t)t * 2048 + j * 256] = make_uint2(pack2h(a.x, a.y), pack2h(a.z, a.w));
                dl[(size_t)t * 2048 + j * 256] = make_uint2(pack2l(a.x, a.y), pack2l(a.z, a.w));
            }
    } else {
        float4* dst = (float4*)g_vre + dbase;
#pragma unroll
        for (int t = 0; t < 8; t++)
#pragma unroll
            for (int j = 0; j < 4; j++)
                dst[(size_t)t * 2048 + j * 256] = acc[t][j];
    }
}

// ---------------------------------------------------------------------------
// Bucketed attention: tensorized dots (bf16x3 mma), fp32 softmax + out.
// smem = 104448 B (proven R13 layout; sd overlays q, v2 overlays k2).
// ---------------------------------------------------------------------------
#define OFF_QH  0
#define OFF_QL  17408
#define OFF_K2H 34816
#define OFF_K2L 69632
#define ATTN_SMEM 104448

__global__ __launch_bounds__(256)
void attn_k(void)
{
    extern __shared__ float smf[];
    char* smc = (char*)smf;
    const uint32_t sb = smem_u32(smf);
    float* sd = smf;                     // overlays q region after dots
    float* skv = smf + OFF_K2H / 4;      // v2 overlay (fp32, stride 128)
    const int u = blockIdx.x, bh = blockIdx.y, tid = threadIdx.x;
    const size_t boff = ((size_t)bh * 4096 + u * 64) * 128;
    const size_t reoff = ((size_t)bh * 64 + u) * 8192;

    {
        const uint4* qh = (const uint4*)g_qbh + (boff >> 3);
        const uint4* ql = (const uint4*)g_qbl + (boff >> 3);
#pragma unroll
        for (int c = 0; c < 4; c++) {
            int idx = tid + c * 256;
            uint32_t so = (idx >> 4) * 272 + (idx & 15) * 16;
            *(uint4*)(smc + OFF_QH + so) = qh[idx];
            *(uint4*)(smc + OFF_QL + so) = ql[idx];
        }
        const uint4* krh = (const uint4*)g_krh + (reoff >> 3);
        const uint4* krl = (const uint4*)g_krl + (reoff >> 3);
        const uint4* kbh = (const uint4*)g_kbh + (boff >> 3);
        const uint4* kbl = (const uint4*)g_kbl + (boff >> 3);
#pragma unroll
        for (int c = 0; c < 8; c++) {
            int idx = tid + c * 256;
            int r = idx >> 4;
            uint32_t so = r * 272 + (idx & 15) * 16;
            *(uint4*)(smc + OFF_K2H + so) = (r < 64) ? krh[idx] : kbh[idx - 1024];
            *(uint4*)(smc + OFF_K2L + so) = (r < 64) ? krl[idx] : kbl[idx - 1024];
        }
    }
    __syncthreads();

    {
        const int lane = tid & 31, wid = tid >> 5;
        const int wm = wid >> 2, wn = wid & 3;
        const int arow = (lane & 7) + ((lane >> 3) & 1) * 8;
        const int acol = ((lane >> 4) & 1) * 8;
        const int brow = (lane & 7) + ((lane >> 4) & 1) * 8;
        const int bcol = ((lane >> 3) & 1) * 8;
        float acc[2][4][4];
#pragma unroll
        for (int i = 0; i < 2; i++)
#pragma unroll
            for (int j = 0; j < 4; j++)
#pragma unroll
                for (int r = 0; r < 4; r++) acc[i][j][r] = 0.f;

#pragma unroll
        for (int kc = 0; kc < 8; kc++) {
            uint32_t bh[4][2], bl[4][2];
#pragma unroll
            for (int jj = 0; jj < 2; jj++) {
                uint32_t ba = sb + OFF_K2H + ((wn * 32 + jj * 16 + brow) * 136 + kc * 16 + bcol) * 2;
                uint32_t rb[4];
                ldsm4(rb, ba);
                bh[jj * 2][0] = rb[0]; bh[jj * 2][1] = rb[1];
                bh[jj * 2 + 1][0] = rb[2]; bh[jj * 2 + 1][1] = rb[3];
                ldsm4(rb, ba + (OFF_K2L - OFF_K2H));
                bl[jj * 2][0] = rb[0]; bl[jj * 2][1] = rb[1];
                bl[jj * 2 + 1][0] = rb[2]; bl[jj * 2 + 1][1] = rb[3];
            }
#pragma unroll
            for (int i = 0; i < 2; i++) {
                uint32_t aa = sb + OFF_QH + ((wm * 32 + i * 16 + arow) * 136 + kc * 16 + acol) * 2;
                uint32_t ah[4], al[4];
                ldsm4(ah, aa);
                ldsm4(al, aa + (OFF_QL - OFF_QH));
#pragma unroll
                for (int j = 0; j < 4; j++) mma16816(acc[i][j], ah, bh[j]);
#pragma unroll
                for (int j = 0; j < 4; j++) mma16816(acc[i][j], ah, bl[j]);
#pragma unroll
                for (int j = 0; j < 4; j++) mma16816(acc[i][j], al, bh[j]);
            }
        }
        __syncthreads();   // all q reads complete before sd overlays the q region
        const float sc = 0.03125f;     // 1024^-0.5
#pragma unroll
        for (int i = 0; i < 2; i++)
#pragma unroll
            for (int j = 0; j < 4; j++) {
                int row = wm * 32 + i * 16 + (lane >> 2);
                int col = wn * 32 + j * 8 + (lane & 3) * 2;
                *(float2*)&sd[row * 130 + col] = make_float2(acc[i][j][0] * sc, acc[i][j][1] * sc);
                *(float2*)&sd[(row + 8) * 130 + col] = make_float2(acc[i][j][2] * sc, acc[i][j][3] * sc);
            }
    }
    __syncthreads();

    {
        const int row = tid >> 2;
        float* rp = sd + row * 130 + (tid & 3) * 32;
        float m = -1e30f;
#pragma unroll
        for (int j = 0; j < 32; j++) m = fmaxf(m, rp[(j + tid) & 31]);
        m = fmaxf(m, __shfl_xor_sync(0xffffffffu, m, 1, 4));
        m = fmaxf(m, __shfl_xor_sync(0xffffffffu, m, 2, 4));
        float s = 0.f;
#pragma unroll
        for (int j = 0; j < 32; j++) {
            int jj = (j + tid) & 31;
            float e = __expf(rp[jj] - m);
            rp[jj] = e;
            s += e;
        }
        s += __shfl_xor_sync(0xffffffffu, s, 1, 4);
        s += __shfl_xor_sync(0xffffffffu, s, 2, 4);
        float inv = 1.f / s;
#pragma unroll
        for (int j = 0; j < 32; j++) { int jj = (j + tid) & 31; rp[jj] *= inv; }

        float4* skv4 = (float4*)skv;
        const float4* vre = (const float4*)(g_vre + reoff);
        const float4* vg = (const float4*)(g_v + boff);
#pragma unroll
        for (int c = 0; c < 8; c++) {
            int idx = tid + c * 256;
            skv4[idx] = vre[idx];
            skv4[idx + 2048] = vg[idx];
        }
    }
    __syncthreads();

    {
        const int ti = (tid >> 4) * 4, te = (tid & 15) * 8;
        float acc[4][8];
#pragma unroll
        for (int ii = 0; ii < 4; ii++)
#pragma unroll
            for (int jj = 0; jj < 8; jj++) acc[ii][jj] = 0.f;
        for (int j = 0; j < 128; j++) {
            float a[4];
#pragma unroll
            for (int ii = 0; ii < 4; ii++) a[ii] = sd[(ti + ii) * 130 + j];
            float4 b0 = *(const float4*)&skv[j * 128 + te];
            float4 b1 = *(const float4*)&skv[j * 128 + te + 4];
#pragma unroll
            for (int ii = 0; ii < 4; ii++) {
                acc[ii][0] += a[ii] * b0.x; acc[ii][1] += a[ii] * b0.y;
                acc[ii][2] += a[ii] * b0.z; acc[ii][3] += a[ii] * b0.w;
                acc[ii][4] += a[ii] * b1.x; acc[ii][5] += a[ii] * b1.y;
                acc[ii][6] += a[ii] * b1.z; acc[ii][7] += a[ii] * b1.w;
            }
        }
        const int bb = bh >> 3, hh = bh & 7;
#pragma unroll
        for (int ii = 0; ii < 4; ii++) {
            size_t base = (size_t)(bb * 4096 + u * 64 + ti + ii) * 1024 + hh * 128 + te;
            uint4 hv = make_uint4(pack2h(acc[ii][0], acc[ii][1]), pack2h(acc[ii][2], acc[ii][3]),
                                  pack2h(acc[ii][4], acc[ii][5]), pack2h(acc[ii][6], acc[ii][7]));
            uint4 lv = make_uint4(pack2l(acc[ii][0], acc[ii][1]), pack2l(acc[ii][2], acc[ii][3]),
                                  pack2l(acc[ii][4], acc[ii][5]), pack2l(acc[ii][6], acc[ii][7]));
            *(uint4*)(g_ah + base) = hv;
            *(uint4*)(g_al + base) = lv;
        }
    }
}

// ---------------------------------------------------------------------------
extern "C" void kernel_launch(void* const* d_in, const int* in_sizes, int n_in,
                              void* d_out, int out_size)
{
    const float* x       = (const float*)d_in[0];
    const float* w_qkv   = (const float*)d_in[1];
    const float* sort_w  = (const float*)d_in[2];
    const float* w_out   = (const float*)d_in[3];
    const float* b_out   = (const float*)d_in[4];
    const float* noise_u = (const float*)d_in[5];
    float* out = (float*)d_out;

    __nv_bfloat16 *xh, *xl, *wqh, *wql, *woh, *wol, *ah, *al;
    cudaGetSymbolAddress((void**)&xh,  g_xh);  cudaGetSymbolAddress((void**)&xl,  g_xl);
    cudaGetSymbolAddress((void**)&wqh, g_wqh); cudaGetSymbolAddress((void**)&wql, g_wql);
    cudaGetSymbolAddress((void**)&woh, g_woh); cudaGetSymbolAddress((void**)&wol, g_wol);
    cudaGetSymbolAddress((void**)&ah,  g_ah);  cudaGetSymbolAddress((void**)&al,  g_al);

    (void)cudaFuncSetAttribute(attn_k, cudaFuncAttributeMaxDynamicSharedMemorySize, ATTN_SMEM);
    (void)cudaFuncSetAttribute(mma_gemm<0>, cudaFuncAttributeMaxDynamicSharedMemorySize, 81920);
    (void)cudaFuncSetAttribute(mma_gemm<1>, cudaFuncAttributeMaxDynamicSharedMemorySize, 81920);

    // prepass: bf16 hi/lo splits
    split_k<<<16384, 256>>>((const float4*)x, (uint2*)xh, (uint2*)xl);
    split_k<<<3072, 256>>>((const float4*)w_qkv, (uint2*)wqh, (uint2*)wql);
    split_k<<<1024, 256>>>((const float4*)w_out, (uint2*)woh, (uint2*)wol);

    // 1) qkv = x @ w_qkv^T  (tensor bf16x3), q/k bf16 splits + k/v fp32
    mma_gemm<0><<<dim3(24, 128), 256, 81920>>>(xh, xl, wqh, wql, nullptr, nullptr);
    // 2) sinkhorn R
    sinkhorn_k<<<32, 256>>>(sort_w, noise_u);
    // 3) k_re (bf16 split) / v_re (fp32), u-tiled
    permute_tiled_k<<<dim3(4, 8, 32), 256>>>();
    // 4) bucketed attention (tensor dots) -> g_ah/g_al
    attn_k<<<dim3(64, 32), 256, ATTN_SMEM>>>();
    // 5) out = attn @ w_out^T + b_out  (tensor bf16x3)
    mma_gemm<1><<<dim3(8, 128), 256, 81920>>>(ah, al, woh, wol, out, b_out);
}

// round 16
// speedup vs baseline: 1.2120x; 1.0378x over previous
#include <cuda_runtime.h>
#include <cuda_bf16.h>
#include <cstdint>

// B=4, T=4096, D=1024, H=8, BUCKETS=64, DH=128, BSZ=64
#define NELEM 16777216

__device__ float g_k[NELEM];
__device__ float g_v[NELEM];
__device__ float g_R[131072];
// bf16 operands
__device__ __nv_bfloat16 g_qbh[NELEM], g_qbl[NELEM];       // q hi/lo (head-major)
__device__ __nv_bfloat16 g_kbh[NELEM], g_kbl[NELEM];       // k hi/lo
__device__ __nv_bfloat16 g_vbh[NELEM], g_vbl[NELEM];       // v hi/lo
__device__ __nv_bfloat16 g_krh[NELEM], g_krl[NELEM];       // k_re hi/lo
__device__ __nv_bfloat16 g_vrh[NELEM], g_vrl[NELEM];       // v_re hi/lo
__device__ __nv_bfloat16 g_xh[16777216], g_xl[16777216];   // x  [16384][1024]
__device__ __nv_bfloat16 g_ah[16777216], g_al[16777216];   // attn out [16384][1024]
__device__ __nv_bfloat16 g_wqh[3145728], g_wql[3145728];   // w_qkv [3072][1024]
__device__ __nv_bfloat16 g_woh[1048576], g_wol[1048576];   // w_out [1024][1024]

// ---------------- helpers ----------------
__device__ __forceinline__ uint32_t smem_u32(const void* p) {
    uint32_t a;
    asm("{ .reg .u64 t; cvta.to.shared.u64 t, %1; cvt.u32.u64 %0, t; }" : "=r"(a) : "l"(p));
    return a;
}
#define CP16(dst, src) asm volatile("cp.async.cg.shared.global [%0], [%1], 16;" :: "r"(dst), "l"(src))
#define CPCOMMIT()     asm volatile("cp.async.commit_group;" ::: "memory")
#define CPWAIT0()      asm volatile("cp.async.wait_group 0;" ::: "memory")

__device__ __forceinline__ void ldsm4(uint32_t* r, uint32_t a) {
    asm volatile("ldmatrix.sync.aligned.m8n8.x4.shared.b16 {%0,%1,%2,%3}, [%4];"
        : "=r"(r[0]), "=r"(r[1]), "=r"(r[2]), "=r"(r[3]) : "r"(a));
}
__device__ __forceinline__ void ldsm4t(uint32_t* r, uint32_t a) {
    asm volatile("ldmatrix.sync.aligned.m8n8.x4.trans.shared.b16 {%0,%1,%2,%3}, [%4];"
        : "=r"(r[0]), "=r"(r[1]), "=r"(r[2]), "=r"(r[3]) : "r"(a));
}
__device__ __forceinline__ void mma16816(float* c, const uint32_t* a, const uint32_t* b) {
    asm volatile("mma.sync.aligned.m16n8k16.row.col.f32.bf16.bf16.f32 "
        "{%0,%1,%2,%3}, {%4,%5,%6,%7}, {%8,%9}, {%0,%1,%2,%3};"
        : "+f"(c[0]), "+f"(c[1]), "+f"(c[2]), "+f"(c[3])
        : "r"(a[0]), "r"(a[1]), "r"(a[2]), "r"(a[3]), "r"(b[0]), "r"(b[1]));
}
__device__ __forceinline__ void bf_split(float v, unsigned short& h, unsigned short& l) {
    __nv_bfloat16 hb = __float2bfloat16_rn(v);
    h = __bfloat16_as_ushort(hb);
    l = __bfloat16_as_ushort(__float2bfloat16_rn(v - __bfloat162float(hb)));
}
__device__ __forceinline__ uint32_t pack2h(float a, float b) {
    unsigned short h0, l0, h1, l1;
    bf_split(a, h0, l0); bf_split(b, h1, l1);
    return (uint32_t)h0 | ((uint32_t)h1 << 16);
}
__device__ __forceinline__ uint32_t pack2l(float a, float b) {
    unsigned short h0, l0, h1, l1;
    bf_split(a, h0, l0); bf_split(b, h1, l1);
    return (uint32_t)l0 | ((uint32_t)l1 << 16);
}

// ---------------------------------------------------------------------------
// Fused prepass: split x / w_qkv / w_out into bf16 hi/lo (one launch)
// float4 counts: x 4194304, w_qkv 786432, w_out 262144 -> 5242880 total
// ---------------------------------------------------------------------------
__global__ __launch_bounds__(256)
void split_all_k(const float4* __restrict__ x, const float4* __restrict__ wq,
                 const float4* __restrict__ wo)
{
    int i = blockIdx.x * 256 + threadIdx.x;
    const float4* src;
    uint2 *hi, *lo;
    int j = i;
    if (i < 4194304) { src = x; hi = (uint2*)g_xh; lo = (uint2*)g_xl; }
    else if (i < 4980736) { j = i - 4194304; src = wq; hi = (uint2*)g_wqh; lo = (uint2*)g_wql; }
    else { j = i - 4980736; src = wo; hi = (uint2*)g_woh; lo = (uint2*)g_wol; }
    float4 v = src[j];
    hi[j] = make_uint2(pack2h(v.x, v.y), pack2h(v.z, v.w));
    lo[j] = make_uint2(pack2l(v.x, v.y), pack2l(v.z, v.w));
}

// ---------------------------------------------------------------------------
// bf16x3 tensor GEMM: tile 128x128, 2-stage cp.async, ONE sync per chunk,
// 80KB smem -> 2 CTAs/SM (proven best config). Product-major MMA order.
// EPI=0: q/k/v bf16 splits + k/v fp32. EPI=1: C=out + bias.
// ---------------------------------------------------------------------------
template<int EPI>
__global__ __launch_bounds__(256)
void mma_gemm(const __nv_bfloat16* __restrict__ Ah, const __nv_bfloat16* __restrict__ Al,
              const __nv_bfloat16* __restrict__ Bh, const __nv_bfloat16* __restrict__ Bl,
              float* __restrict__ C, const float* __restrict__ bias)
{
    extern __shared__ char sm[];
    const uint32_t sb = smem_u32(sm);
    const int tid = threadIdx.x, lane = tid & 31, wid = tid >> 5;
    const int wm = wid >> 2, wn = wid & 3;
    const int m0 = blockIdx.y * 128, n0 = blockIdx.x * 128;
    const int prow = tid >> 1, pseg0 = (tid & 1) * 2;

    float acc[4][4][4];
#pragma unroll
    for (int i = 0; i < 4; i++)
#pragma unroll
        for (int j = 0; j < 4; j++)
#pragma unroll
            for (int r = 0; r < 4; r++) acc[i][j][r] = 0.f;

    const size_t arow = (size_t)(m0 + prow) * 1024;
    const size_t brow = (size_t)(n0 + prow) * 1024;

#define ISSUE(c, s) do {                                                        \
    const int k0_ = (c) * 32;                                                   \
    const uint32_t db = sb + (s) * 40960 + prow * 80;                           \
    _Pragma("unroll")                                                           \
    for (int t = 0; t < 2; t++) {                                               \
        const int sg = pseg0 + t;                                               \
        const uint32_t d0 = db + sg * 16;                                       \
        const size_t go = k0_ + sg * 8;                                         \
        CP16(d0,         Ah + arow + go);                                       \
        CP16(d0 + 10240, Al + arow + go);                                       \
        CP16(d0 + 20480, Bh + brow + go);                                       \
        CP16(d0 + 30720, Bl + brow + go);                                       \
    }                                                                           \
} while (0)

    ISSUE(0, 0); CPCOMMIT();
#pragma unroll 1
    for (int c = 0; c < 32; c++) {
        CPWAIT0();
        __syncthreads();
        if (c + 1 < 32) { ISSUE(c + 1, (c + 1) & 1); CPCOMMIT(); }
        const uint32_t base = sb + (c & 1) * 40960;
#pragma unroll
        for (int ks = 0; ks < 2; ks++) {
            uint32_t bh[4][2], bl[4][2];
            const int br2 = wn * 32 + (lane & 7) + ((lane >> 4) & 1) * 8;
            const int bc = ks * 16 + ((lane >> 3) & 1) * 8;
#pragma unroll
            for (int jj = 0; jj < 2; jj++) {
                uint32_t ba = base + 20480 + ((br2 + jj * 16) * 40 + bc) * 2;
                uint32_t rb[4];
                ldsm4(rb, ba);
                bh[jj * 2][0] = rb[0]; bh[jj * 2][1] = rb[1];
                bh[jj * 2 + 1][0] = rb[2]; bh[jj * 2 + 1][1] = rb[3];
                ldsm4(rb, ba + 10240);
                bl[jj * 2][0] = rb[0]; bl[jj * 2][1] = rb[1];
                bl[jj * 2 + 1][0] = rb[2]; bl[jj * 2 + 1][1] = rb[3];
            }
            const int ar = wm * 64 + (lane & 7) + ((lane >> 3) & 1) * 8;
            const int ac = ks * 16 + ((lane >> 4) & 1) * 8;
#pragma unroll
            for (int i = 0; i < 4; i++) {
                uint32_t aa = base + ((ar + i * 16) * 40 + ac) * 2;
                uint32_t ah[4], al[4];
                ldsm4(ah, aa);
                ldsm4(al, aa + 10240);
#pragma unroll
                for (int j = 0; j < 4; j++) mma16816(acc[i][j], ah, bh[j]);
#pragma unroll
                for (int j = 0; j < 4; j++) mma16816(acc[i][j], ah, bl[j]);
#pragma unroll
                for (int j = 0; j < 4; j++) mma16816(acc[i][j], al, bh[j]);
            }
        }
    }

    const int mrow = lane >> 2, ncol = (lane & 3) * 2;
#pragma unroll
    for (int i = 0; i < 4; i++) {
#pragma unroll
        for (int j = 0; j < 4; j++) {
            const int gm = m0 + wm * 64 + i * 16 + mrow;
            const int gn = n0 + wn * 32 + j * 8 + ncol;
            if (EPI == 0) {
                const int slice = n0 >> 10, h = (n0 >> 7) & 7;
                const int nn = gn & 127;
                size_t e0 = ((size_t)((gm >> 12) * 8 + h) * 4096 + (gm & 4095)) * 128 + nn;
                size_t e1 = ((size_t)(((gm + 8) >> 12) * 8 + h) * 4096 + ((gm + 8) & 4095)) * 128 + nn;
                float c0 = acc[i][j][0], c1 = acc[i][j][1], c2 = acc[i][j][2], c3 = acc[i][j][3];
                if (slice == 0) {            // q: bf16 hi/lo only
                    *(uint32_t*)(g_qbh + e0) = pack2h(c0, c1);
                    *(uint32_t*)(g_qbl + e0) = pack2l(c0, c1);
                    *(uint32_t*)(g_qbh + e1) = pack2h(c2, c3);
                    *(uint32_t*)(g_qbl + e1) = pack2l(c2, c3);
                } else if (slice == 1) {     // k: fp32 + bf16 hi/lo
                    *(float2*)(g_k + e0) = make_float2(c0, c1);
                    *(float2*)(g_k + e1) = make_float2(c2, c3);
                    *(uint32_t*)(g_kbh + e0) = pack2h(c0, c1);
                    *(uint32_t*)(g_kbl + e0) = pack2l(c0, c1);
                    *(uint32_t*)(g_kbh + e1) = pack2h(c2, c3);
                    *(uint32_t*)(g_kbl + e1) = pack2l(c2, c3);
                } else {                     // v: fp32 + bf16 hi/lo
                    *(float2*)(g_v + e0) = make_float2(c0, c1);
                    *(float2*)(g_v + e1) = make_float2(c2, c3);
                    *(uint32_t*)(g_vbh + e0) = pack2h(c0, c1);
                    *(uint32_t*)(g_vbl + e0) = pack2l(c0, c1);
                    *(uint32_t*)(g_vbh + e1) = pack2h(c2, c3);
                    *(uint32_t*)(g_vbl + e1) = pack2l(c2, c3);
                }
            } else {
                float2 bv = *(const float2*)(bias + gn);
                *(float2*)(C + (size_t)gm * 1024 + gn) =
                    make_float2(acc[i][j][0] + bv.x, acc[i][j][1] + bv.y);
                *(float2*)(C + (size_t)(gm + 8) * 1024 + gn) =
                    make_float2(acc[i][j][2] + bv.x, acc[i][j][3] + bv.y);
            }
        }
    }
}

// ---------------------------------------------------------------------------
// Sinkhorn sorting matrix (reads fp32 g_k)
// ---------------------------------------------------------------------------
__global__ __launch_bounds__(256)
void sinkhorn_k(const float* __restrict__ sort_w, const float* __restrict__ noise_u)
{
    __shared__ float sh[8192];
    const int bh = blockIdx.x, h = bh & 7, tid = threadIdx.x;
#pragma unroll 1
    for (int c = 0; c < 32; c++) {
        int idx = tid + c * 256;
        int uu = idx >> 7, dd = idx & 127;
        const float* kp = g_k + ((size_t)bh * 4096 + uu * 64) * 128 + dd;
        float s = 0.f;
#pragma unroll 8
        for (int i = 0; i < 64; i++) s += kp[(size_t)i * 128];
        sh[idx] = s;
    }
    __syncthreads();
    float logit[16];
#pragma unroll 1
    for (int c = 0; c < 16; c++) {
        int idx = tid + c * 256;
        int uu = idx >> 6, vv = idx & 63;
        const float* wp = sort_w + h * 8192 + vv;
        const float* bp = sh + uu * 128;
        float s = 0.f;
#pragma unroll 8
        for (int d = 0; d < 128; d++) s += bp[d] * wp[d * 64];
        float nu = noise_u[(size_t)bh * 4096 + idx];
        float g = -logf(-logf(nu + 1e-4f) + 1e-4f);
        logit[c] = (logf(fmaxf(s, 0.f) + 1e-6f) + g) * (1.0f / 0.75f);
    }
    __syncthreads();
#pragma unroll
    for (int c = 0; c < 16; c++) sh[tid + c * 256] = logit[c];
    __syncthreads();
    for (int it = 0; it < 5; it++) {
        if (tid < 64) {
            float m = -1e30f;
            for (int v = 0; v < 64; v++) m = fmaxf(m, sh[tid * 64 + ((v + tid) & 63)]);
            float s = 0.f;
            for (int v = 0; v < 64; v++) s += expf(sh[tid * 64 + ((v + tid) & 63)] - m);
            float l = m + logf(s);
            for (int v = 0; v < 64; v++) sh[tid * 64 + ((v + tid) & 63)] -= l;
        }
        __syncthreads();
        if (tid < 64) {
            float m = -1e30f;
            for (int u = 0; u < 64; u++) m = fmaxf(m, sh[u * 64 + tid]);
            float s = 0.f;
            for (int u = 0; u < 64; u++) s += expf(sh[u * 64 + tid] - m);
            float l = m + logf(s);
            for (int u = 0; u < 64; u++) sh[u * 64 + tid] -= l;
        }
        __syncthreads();
    }
#pragma unroll
    for (int c = 0; c < 16; c++) {
        int idx = tid + c * 256;
        int uu = idx >> 6, vv = idx & 63;
        g_R[(size_t)bh * 4096 + idx] = (vv < uu) ? expf(sh[idx]) : 0.f;
    }
}

// ---------------------------------------------------------------------------
// k_re/v_re soft permute, u-tiled; BOTH outputs bf16 hi/lo now.
// grid: (4, 8, 32) = (arr*2+half, utile, bh)
// ---------------------------------------------------------------------------
__global__ __launch_bounds__(256)
void permute_tiled_k(void)
{
    const int arr = blockIdx.x >> 1, half = blockIdx.x & 1;
    const int u0 = blockIdx.y * 8, bh = blockIdx.z;
    const int tid = threadIdx.x;

    __shared__ float rr[512];
    for (int i = tid; i < 512; i += 256)
        rr[i] = g_R[(size_t)bh * 4096 + (u0 + (i >> 6)) * 64 + (i & 63)];
    __syncthreads();

    const float4* src = (const float4*)(arr == 0 ? g_k : g_v) + (size_t)bh * 131072 + half * 1024 + tid;
    const size_t dbase = (size_t)(bh * 64 + u0) * 2048 + half * 1024 + tid;

    float4 acc[8][4];
#pragma unroll
    for (int t = 0; t < 8; t++)
#pragma unroll
        for (int j = 0; j < 4; j++) acc[t][j] = make_float4(0.f, 0.f, 0.f, 0.f);

    const int vmax = u0 + 7;
#pragma unroll 1
    for (int vv = 0; vv < vmax; vv++) {
        float4 d[4];
#pragma unroll
        for (int j = 0; j < 4; j++) d[j] = src[(size_t)vv * 2048 + j * 256];
#pragma unroll
        for (int t = 0; t < 8; t++) {
            float r = rr[t * 64 + vv];
#pragma unroll
            for (int j = 0; j < 4; j++) {
                acc[t][j].x += r * d[j].x; acc[t][j].y += r * d[j].y;
                acc[t][j].z += r * d[j].z; acc[t][j].w += r * d[j].w;
            }
        }
    }
    uint2* dh = (uint2*)(arr == 0 ? g_krh : g_vrh) + dbase;
    uint2* dl = (uint2*)(arr == 0 ? g_krl : g_vrl) + dbase;
#pragma unroll
    for (int t = 0; t < 8; t++)
#pragma unroll
        for (int j = 0; j < 4; j++) {
            float4 a = acc[t][j];
            dh[(size_t)t * 2048 + j * 256] = make_uint2(pack2h(a.x, a.y), pack2h(a.z, a.w));
            dl[(size_t)t * 2048 + j * 256] = make_uint2(pack2l(a.x, a.y), pack2l(a.z, a.w));
        }
}

// ---------------------------------------------------------------------------
// Bucketed attention: bf16x3 tensor dots AND out phases. smem = 104448 B.
// regions: q/probs [0,34816) | k2h/v2h [34816,69632) | k2l/{sd,v2l} [69632,104448)
// ---------------------------------------------------------------------------
#define OFF_QH   0
#define OFF_QL   17408
#define OFF_K2H  34816
#define OFF_K2L  69632
#define OFF_SD   69632        // fp32 64x130, overlays k2l after dots
#define OFF_PH   0            // probs hi, overlays q after dots
#define OFF_PL   17408
#define OFF_V2H  34816        // overlays k2h after dots
#define OFF_V2L  69632        // overlays sd after conversion
#define ATTN_SMEM 104448

__global__ __launch_bounds__(256)
void attn_k(void)
{
    extern __shared__ float smf[];
    char* smc = (char*)smf;
    const uint32_t sb = smem_u32(smf);
    float* sd = smf + OFF_SD / 4;
    const int u = blockIdx.x, bh = blockIdx.y, tid = threadIdx.x;
    const int lane = tid & 31, wid = tid >> 5;
    const int wm = wid >> 2, wn = wid & 3;
    const size_t boff = ((size_t)bh * 4096 + u * 64) * 128;
    const size_t reoff = ((size_t)bh * 64 + u) * 8192;

    // ---- phase 0: load q (hi/lo) and k2 = [k_re; b_k] (hi/lo) ----
    {
        const uint4* qh = (const uint4*)g_qbh + (boff >> 3);
        const uint4* ql = (const uint4*)g_qbl + (boff >> 3);
#pragma unroll
        for (int c = 0; c < 4; c++) {
            int idx = tid + c * 256;
            uint32_t so = (idx >> 4) * 272 + (idx & 15) * 16;
            *(uint4*)(smc + OFF_QH + so) = qh[idx];
            *(uint4*)(smc + OFF_QL + so) = ql[idx];
        }
        const uint4* krh = (const uint4*)g_krh + (reoff >> 3);
        const uint4* krl = (const uint4*)g_krl + (reoff >> 3);
        const uint4* kbh = (const uint4*)g_kbh + (boff >> 3);
        const uint4* kbl = (const uint4*)g_kbl + (boff >> 3);
#pragma unroll
        for (int c = 0; c < 8; c++) {
            int idx = tid + c * 256;
            int r = idx >> 4;
            uint32_t so = r * 272 + (idx & 15) * 16;
            *(uint4*)(smc + OFF_K2H + so) = (r < 64) ? krh[idx] : kbh[idx - 1024];
            *(uint4*)(smc + OFF_K2L + so) = (r < 64) ? krl[idx] : kbl[idx - 1024];
        }
    }
    __syncthreads();                                   // B1

    // ---- phase 1: dots = q @ k2^T (bf16x3 mma) ----
    {
        const int arow = (lane & 7) + ((lane >> 3) & 1) * 8;
        const int acol = ((lane >> 4) & 1) * 8;
        const int brow = (lane & 7) + ((lane >> 4) & 1) * 8;
        const int bcol = ((lane >> 3) & 1) * 8;
        float acc[2][4][4];
#pragma unroll
        for (int i = 0; i < 2; i++)
#pragma unroll
            for (int j = 0; j < 4; j++)
#pragma unroll
                for (int r = 0; r < 4; r++) acc[i][j][r] = 0.f;

#pragma unroll
        for (int kc = 0; kc < 8; kc++) {
            uint32_t bh[4][2], bl[4][2];
#pragma unroll
            for (int jj = 0; jj < 2; jj++) {
                uint32_t ba = sb + OFF_K2H + ((wn * 32 + jj * 16 + brow) * 136 + kc * 16 + bcol) * 2;
                uint32_t rb[4];
                ldsm4(rb, ba);
                bh[jj * 2][0] = rb[0]; bh[jj * 2][1] = rb[1];
                bh[jj * 2 + 1][0] = rb[2]; bh[jj * 2 + 1][1] = rb[3];
                ldsm4(rb, ba + (OFF_K2L - OFF_K2H));
                bl[jj * 2][0] = rb[0]; bl[jj * 2][1] = rb[1];
                bl[jj * 2 + 1][0] = rb[2]; bl[jj * 2 + 1][1] = rb[3];
            }
#pragma unroll
            for (int i = 0; i < 2; i++) {
                uint32_t aa = sb + OFF_QH + ((wm * 32 + i * 16 + arow) * 136 + kc * 16 + acol) * 2;
                uint32_t ah[4], al[4];
                ldsm4(ah, aa);
                ldsm4(al, aa + (OFF_QL - OFF_QH));
#pragma unroll
                for (int j = 0; j < 4; j++) mma16816(acc[i][j], ah, bh[j]);
#pragma unroll
                for (int j = 0; j < 4; j++) mma16816(acc[i][j], ah, bl[j]);
#pragma unroll
                for (int j = 0; j < 4; j++) mma16816(acc[i][j], al, bh[j]);
            }
        }
        __syncthreads();                               // B2: all k2l reads done
        const float sc = 0.03125f;                     // 1024^-0.5
#pragma unroll
        for (int i = 0; i < 2; i++)
#pragma unroll
            for (int j = 0; j < 4; j++) {
                int row = wm * 32 + i * 16 + (lane >> 2);
                int col = wn * 32 + j * 8 + (lane & 3) * 2;
                *(float2*)&sd[row * 130 + col] = make_float2(acc[i][j][0] * sc, acc[i][j][1] * sc);
                *(float2*)&sd[(row + 8) * 130 + col] = make_float2(acc[i][j][2] * sc, acc[i][j][3] * sc);
            }
    }
    __syncthreads();                                   // B3

    // ---- phase 2: softmax in place on sd + fill v2h (k2h region dead) ----
    {
        const int row = tid >> 2;
        float* rp = sd + row * 130 + (tid & 3) * 32;
        float m = -1e30f;
#pragma unroll
        for (int j = 0; j < 32; j++) m = fmaxf(m, rp[(j + tid) & 31]);
        m = fmaxf(m, __shfl_xor_sync(0xffffffffu, m, 1, 4));
        m = fmaxf(m, __shfl_xor_sync(0xffffffffu, m, 2, 4));
        float s = 0.f;
#pragma unroll
        for (int j = 0; j < 32; j++) {
            int jj = (j + tid) & 31;
            float e = __expf(rp[jj] - m);
            rp[jj] = e;
            s += e;
        }
        s += __shfl_xor_sync(0xffffffffu, s, 1, 4);
        s += __shfl_xor_sync(0xffffffffu, s, 2, 4);
        float inv = 1.f / s;
#pragma unroll
        for (int j = 0; j < 32; j++) { int jj = (j + tid) & 31; rp[jj] *= inv; }

        const uint4* vrh = (const uint4*)g_vrh + (reoff >> 3);
        const uint4* vbh = (const uint4*)g_vbh + (boff >> 3);
#pragma unroll
        for (int c = 0; c < 8; c++) {
            int idx = tid + c * 256;
            int r = idx >> 4;
            uint32_t so = r * 272 + (idx & 15) * 16;
            *(uint4*)(smc + OFF_V2H + so) = (r < 64) ? vrh[idx] : vbh[idx - 1024];
        }
    }
    __syncthreads();                                   // B4

    // ---- phase 3: convert sd fp32 -> probs bf16 hi/lo (disjoint regions) ----
    {
        const int row = tid >> 2, c0 = (tid & 3) * 32;
        const float* rp = sd + row * 130 + c0;
        uint32_t* ph = (uint32_t*)(smc + OFF_PH + (row * 136 + c0) * 2);
        uint32_t* pl = (uint32_t*)(smc + OFF_PL + (row * 136 + c0) * 2);
#pragma unroll
        for (int j = 0; j < 16; j++) {
            float a = rp[j * 2], b = rp[j * 2 + 1];
            ph[j] = pack2h(a, b);
            pl[j] = pack2l(a, b);
        }
    }
    __syncthreads();                                   // B5

    // ---- phase 4: fill v2l (sd region dead) ----
    {
        const uint4* vrl = (const uint4*)g_vrl + (reoff >> 3);
        const uint4* vbl = (const uint4*)g_vbl + (boff >> 3);
#pragma unroll
        for (int c = 0; c < 8; c++) {
            int idx = tid + c * 256;
            int r = idx >> 4;
            uint32_t so = r * 272 + (idx & 15) * 16;
            *(uint4*)(smc + OFF_V2L + so) = (r < 64) ? vrl[idx] : vbl[idx - 1024];
        }
    }
    __syncthreads();                                   // B6

    // ---- phase 5: out = probs @ v2 (bf16x3, B via trans ldmatrix) ----
    {
        const int arow = (lane & 7) + ((lane >> 3) & 1) * 8;
        const int acol = ((lane >> 4) & 1) * 8;
        const int trow = (lane & 7) + ((lane >> 3) & 1) * 8;   // k-row within 16
        const int tcol = ((lane >> 4) & 1) * 8;                // n offset within 16
        float acc[2][4][4];
#pragma unroll
        for (int i = 0; i < 2; i++)
#pragma unroll
            for (int j = 0; j < 4; j++)
#pragma unroll
                for (int r = 0; r < 4; r++) acc[i][j][r] = 0.f;

#pragma unroll
        for (int kc = 0; kc < 8; kc++) {
            uint32_t bh[4][2], bl[4][2];
#pragma unroll
            for (int jo = 0; jo < 2; jo++) {
                uint32_t ba = sb + OFF_V2H + ((kc * 16 + trow) * 136 + wn * 32 + jo * 16 + tcol) * 2;
                uint32_t rb[4];
                ldsm4t(rb, ba);
                bh[jo * 2][0] = rb[0]; bh[jo * 2][1] = rb[1];
                bh[jo * 2 + 1][0] = rb[2]; bh[jo * 2 + 1][1] = rb[3];
                ldsm4t(rb, ba + (OFF_V2L - OFF_V2H));
                bl[jo * 2][0] = rb[0]; bl[jo * 2][1] = rb[1];
                bl[jo * 2 + 1][0] = rb[2]; bl[jo * 2 + 1][1] = rb[3];
            }
#pragma unroll
            for (int i = 0; i < 2; i++) {
                uint32_t aa = sb + OFF_PH + ((wm * 32 + i * 16 + arow) * 136 + kc * 16 + acol) * 2;
                uint32_t ah[4], al[4];
                ldsm4(ah, aa);
                ldsm4(al, aa + (OFF_PL - OFF_PH));
#pragma unroll
                for (int j = 0; j < 4; j++) mma16816(acc[i][j], ah, bh[j]);
#pragma unroll
                for (int j = 0; j < 4; j++) mma16816(acc[i][j], ah, bl[j]);
#pragma unroll
                for (int j = 0; j < 4; j++) mma16816(acc[i][j], al, bh[j]);
            }
        }

        // epilogue: fragments -> g_ah/g_al (b, t, D)
        const int bb = bh >> 3, hh = bh & 7;
#pragma unroll
        for (int i = 0; i < 2; i++)
#pragma unroll
            for (int j = 0; j < 4; j++) {
                int r0 = wm * 32 + i * 16 + (lane >> 2);
                int col = wn * 32 + j * 8 + (lane & 3) * 2;
                size_t b0 = (size_t)(bb * 4096 + u * 64 + r0) * 1024 + hh * 128 + col;
                size_t b1 = (size_t)(bb * 4096 + u * 64 + r0 + 8) * 1024 + hh * 128 + col;
                *(uint32_t*)(g_ah + b0) = pack2h(acc[i][j][0], acc[i][j][1]);
                *(uint32_t*)(g_al + b0) = pack2l(acc[i][j][0], acc[i][j][1]);
                *(uint32_t*)(g_ah + b1) = pack2h(acc[i][j][2], acc[i][j][3]);
                *(uint32_t*)(g_al + b1) = pack2l(acc[i][j][2], acc[i][j][3]);
            }
    }
}

// ---------------------------------------------------------------------------
extern "C" void kernel_launch(void* const* d_in, const int* in_sizes, int n_in,
                              void* d_out, int out_size)
{
    const float* x       = (const float*)d_in[0];
    const float* w_qkv   = (const float*)d_in[1];
    const float* sort_w  = (const float*)d_in[2];
    const float* w_out   = (const float*)d_in[3];
    const float* b_out   = (const float*)d_in[4];
    const float* noise_u = (const float*)d_in[5];
    float* out = (float*)d_out;

    __nv_bfloat16 *xh, *xl, *wqh, *wql, *woh, *wol, *ah, *al;
    cudaGetSymbolAddress((void**)&xh,  g_xh);  cudaGetSymbolAddress((void**)&xl,  g_xl);
    cudaGetSymbolAddress((void**)&wqh, g_wqh); cudaGetSymbolAddress((void**)&wql, g_wql);
    cudaGetSymbolAddress((void**)&woh, g_woh); cudaGetSymbolAddress((void**)&wol, g_wol);
    cudaGetSymbolAddress((void**)&ah,  g_ah);  cudaGetSymbolAddress((void**)&al,  g_al);

    (void)cudaFuncSetAttribute(attn_k, cudaFuncAttributeMaxDynamicSharedMemorySize, ATTN_SMEM);
    (void)cudaFuncSetAttribute(mma_gemm<0>, cudaFuncAttributeMaxDynamicSharedMemorySize, 81920);
    (void)cudaFuncSetAttribute(mma_gemm<1>, cudaFuncAttributeMaxDynamicSharedMemorySize, 81920);

    // prepass: fused bf16 hi/lo splits
    split_all_k<<<20480, 256>>>((const float4*)x, (const float4*)w_qkv, (const float4*)w_out);

    // 1) qkv = x @ w_qkv^T  (tensor bf16x3)
    mma_gemm<0><<<dim3(24, 128), 256, 81920>>>(xh, xl, wqh, wql, nullptr, nullptr);
    // 2) sinkhorn R
    sinkhorn_k<<<32, 256>>>(sort_w, noise_u);
    // 3) k_re / v_re (bf16 splits), u-tiled
    permute_tiled_k<<<dim3(4, 8, 32), 256>>>();
    // 4) bucketed attention (tensor dots + tensor out) -> g_ah/g_al
    attn_k<<<dim3(64, 32), 256, ATTN_SMEM>>>();
    // 5) out = attn @ w_out^T + b_out  (tensor bf16x3)
    mma_gemm<1><<<dim3(8, 128), 256, 81920>>>(ah, al, woh, wol, out, b_out);
}

// round 17
// speedup vs baseline: 1.2268x; 1.0122x over previous
#include <cuda_runtime.h>
#include <cuda_bf16.h>
#include <cstdint>

// B=4, T=4096, D=1024, H=8, BUCKETS=64, DH=128, BSZ=64
#define NELEM 16777216

__device__ float g_k[NELEM];
__device__ float g_v[NELEM];
__device__ float g_R[131072];
// bf16 operands
__device__ __nv_bfloat16 g_qbh[NELEM], g_qbl[NELEM];       // q hi/lo (head-major)
__device__ __nv_bfloat16 g_kbh[NELEM], g_kbl[NELEM];       // k hi/lo
__device__ __nv_bfloat16 g_vbh[NELEM], g_vbl[NELEM];       // v hi/lo
__device__ __nv_bfloat16 g_krh[NELEM], g_krl[NELEM];       // k_re hi/lo
__device__ __nv_bfloat16 g_vrh[NELEM], g_vrl[NELEM];       // v_re hi/lo
__device__ __nv_bfloat16 g_xh[16777216], g_xl[16777216];   // x  [16384][1024]
__device__ __nv_bfloat16 g_ah[16777216], g_al[16777216];   // attn out [16384][1024]
__device__ __nv_bfloat16 g_wqh[3145728], g_wql[3145728];   // w_qkv [3072][1024]
__device__ __nv_bfloat16 g_woh[1048576], g_wol[1048576];   // w_out [1024][1024]

// ---------------- helpers ----------------
__device__ __forceinline__ uint32_t smem_u32(const void* p) {
    uint32_t a;
    asm("{ .reg .u64 t; cvta.to.shared.u64 t, %1; cvt.u32.u64 %0, t; }" : "=r"(a) : "l"(p));
    return a;
}
#define CP16(dst, src) asm volatile("cp.async.cg.shared.global [%0], [%1], 16;" :: "r"(dst), "l"(src))
#define CPCOMMIT()     asm volatile("cp.async.commit_group;" ::: "memory")
#define CPWAIT0()      asm volatile("cp.async.wait_group 0;" ::: "memory")

__device__ __forceinline__ void ldsm4(uint32_t* r, uint32_t a) {
    asm volatile("ldmatrix.sync.aligned.m8n8.x4.shared.b16 {%0,%1,%2,%3}, [%4];"
        : "=r"(r[0]), "=r"(r[1]), "=r"(r[2]), "=r"(r[3]) : "r"(a));
}
__device__ __forceinline__ void ldsm4t(uint32_t* r, uint32_t a) {
    asm volatile("ldmatrix.sync.aligned.m8n8.x4.trans.shared.b16 {%0,%1,%2,%3}, [%4];"
        : "=r"(r[0]), "=r"(r[1]), "=r"(r[2]), "=r"(r[3]) : "r"(a));
}
__device__ __forceinline__ void mma16816(float* c, const uint32_t* a, const uint32_t* b) {
    asm volatile("mma.sync.aligned.m16n8k16.row.col.f32.bf16.bf16.f32 "
        "{%0,%1,%2,%3}, {%4,%5,%6,%7}, {%8,%9}, {%0,%1,%2,%3};"
        : "+f"(c[0]), "+f"(c[1]), "+f"(c[2]), "+f"(c[3])
        : "r"(a[0]), "r"(a[1]), "r"(a[2]), "r"(a[3]), "r"(b[0]), "r"(b[1]));
}
__device__ __forceinline__ void bf_split(float v, unsigned short& h, unsigned short& l) {
    __nv_bfloat16 hb = __float2bfloat16_rn(v);
    h = __bfloat16_as_ushort(hb);
    l = __bfloat16_as_ushort(__float2bfloat16_rn(v - __bfloat162float(hb)));
}
__device__ __forceinline__ uint32_t pack2h(float a, float b) {
    unsigned short h0, l0, h1, l1;
    bf_split(a, h0, l0); bf_split(b, h1, l1);
    return (uint32_t)h0 | ((uint32_t)h1 << 16);
}
__device__ __forceinline__ uint32_t pack2l(float a, float b) {
    unsigned short h0, l0, h1, l1;
    bf_split(a, h0, l0); bf_split(b, h1, l1);
    return (uint32_t)l0 | ((uint32_t)l1 << 16);
}

// ---------------------------------------------------------------------------
// Fused prepass: split x / w_qkv / w_out into bf16 hi/lo (one launch)
// ---------------------------------------------------------------------------
__global__ __launch_bounds__(256)
void split_all_k(const float4* __restrict__ x, const float4* __restrict__ wq,
                 const float4* __restrict__ wo)
{
    int i = blockIdx.x * 256 + threadIdx.x;
    const float4* src;
    uint2 *hi, *lo;
    int j = i;
    if (i < 4194304) { src = x; hi = (uint2*)g_xh; lo = (uint2*)g_xl; }
    else if (i < 4980736) { j = i - 4194304; src = wq; hi = (uint2*)g_wqh; lo = (uint2*)g_wql; }
    else { j = i - 4980736; src = wo; hi = (uint2*)g_woh; lo = (uint2*)g_wol; }
    float4 v = src[j];
    hi[j] = make_uint2(pack2h(v.x, v.y), pack2h(v.z, v.w));
    lo[j] = make_uint2(pack2l(v.x, v.y), pack2l(v.z, v.w));
}

// ---------------------------------------------------------------------------
// bf16x3 tensor GEMM: tile 128x128, 2-stage cp.async, ONE sync per chunk,
// 80KB smem -> 2 CTAs/SM. EPI=0: q/k/v splits + k/v fp32. EPI=1: out + bias.
// ---------------------------------------------------------------------------
template<int EPI>
__global__ __launch_bounds__(256)
void mma_gemm(const __nv_bfloat16* __restrict__ Ah, const __nv_bfloat16* __restrict__ Al,
              const __nv_bfloat16* __restrict__ Bh, const __nv_bfloat16* __restrict__ Bl,
              float* __restrict__ C, const float* __restrict__ bias)
{
    extern __shared__ char sm[];
    const uint32_t sb = smem_u32(sm);
    const int tid = threadIdx.x, lane = tid & 31, wid = tid >> 5;
    const int wm = wid >> 2, wn = wid & 3;
    const int m0 = blockIdx.y * 128, n0 = blockIdx.x * 128;
    const int prow = tid >> 1, pseg0 = (tid & 1) * 2;

    float acc[4][4][4];
#pragma unroll
    for (int i = 0; i < 4; i++)
#pragma unroll
        for (int j = 0; j < 4; j++)
#pragma unroll
            for (int r = 0; r < 4; r++) acc[i][j][r] = 0.f;

    const size_t arow = (size_t)(m0 + prow) * 1024;
    const size_t brow = (size_t)(n0 + prow) * 1024;

#define ISSUE(c, s) do {                                                        \
    const int k0_ = (c) * 32;                                                   \
    const uint32_t db = sb + (s) * 40960 + prow * 80;                           \
    _Pragma("unroll")                                                           \
    for (int t = 0; t < 2; t++) {                                               \
        const int sg = pseg0 + t;                                               \
        const uint32_t d0 = db + sg * 16;                                       \
        const size_t go = k0_ + sg * 8;                                         \
        CP16(d0,         Ah + arow + go);                                       \
        CP16(d0 + 10240, Al + arow + go);                                       \
        CP16(d0 + 20480, Bh + brow + go);                                       \
        CP16(d0 + 30720, Bl + brow + go);                                       \
    }                                                                           \
} while (0)

    ISSUE(0, 0); CPCOMMIT();
#pragma unroll 1
    for (int c = 0; c < 32; c++) {
        CPWAIT0();
        __syncthreads();
        if (c + 1 < 32) { ISSUE(c + 1, (c + 1) & 1); CPCOMMIT(); }
        const uint32_t base = sb + (c & 1) * 40960;
#pragma unroll
        for (int ks = 0; ks < 2; ks++) {
            uint32_t bh[4][2], bl[4][2];
            const int br2 = wn * 32 + (lane & 7) + ((lane >> 4) & 1) * 8;
            const int bc = ks * 16 + ((lane >> 3) & 1) * 8;
#pragma unroll
            for (int jj = 0; jj < 2; jj++) {
                uint32_t ba = base + 20480 + ((br2 + jj * 16) * 40 + bc) * 2;
                uint32_t rb[4];
                ldsm4(rb, ba);
                bh[jj * 2][0] = rb[0]; bh[jj * 2][1] = rb[1];
                bh[jj * 2 + 1][0] = rb[2]; bh[jj * 2 + 1][1] = rb[3];
                ldsm4(rb, ba + 10240);
                bl[jj * 2][0] = rb[0]; bl[jj * 2][1] = rb[1];
                bl[jj * 2 + 1][0] = rb[2]; bl[jj * 2 + 1][1] = rb[3];
            }
            const int ar = wm * 64 + (lane & 7) + ((lane >> 3) & 1) * 8;
            const int ac = ks * 16 + ((lane >> 4) & 1) * 8;
#pragma unroll
            for (int i = 0; i < 4; i++) {
                uint32_t aa = base + ((ar + i * 16) * 40 + ac) * 2;
                uint32_t ah[4], al[4];
                ldsm4(ah, aa);
                ldsm4(al, aa + 10240);
#pragma unroll
                for (int j = 0; j < 4; j++) mma16816(acc[i][j], ah, bh[j]);
#pragma unroll
                for (int j = 0; j < 4; j++) mma16816(acc[i][j], ah, bl[j]);
#pragma unroll
                for (int j = 0; j < 4; j++) mma16816(acc[i][j], al, bh[j]);
            }
        }
    }

    const int mrow = lane >> 2, ncol = (lane & 3) * 2;
#pragma unroll
    for (int i = 0; i < 4; i++) {
#pragma unroll
        for (int j = 0; j < 4; j++) {
            const int gm = m0 + wm * 64 + i * 16 + mrow;
            const int gn = n0 + wn * 32 + j * 8 + ncol;
            if (EPI == 0) {
                const int slice = n0 >> 10, h = (n0 >> 7) & 7;
                const int nn = gn & 127;
                size_t e0 = ((size_t)((gm >> 12) * 8 + h) * 4096 + (gm & 4095)) * 128 + nn;
                size_t e1 = ((size_t)(((gm + 8) >> 12) * 8 + h) * 4096 + ((gm + 8) & 4095)) * 128 + nn;
                float c0 = acc[i][j][0], c1 = acc[i][j][1], c2 = acc[i][j][2], c3 = acc[i][j][3];
                if (slice == 0) {
                    *(uint32_t*)(g_qbh + e0) = pack2h(c0, c1);
                    *(uint32_t*)(g_qbl + e0) = pack2l(c0, c1);
                    *(uint32_t*)(g_qbh + e1) = pack2h(c2, c3);
                    *(uint32_t*)(g_qbl + e1) = pack2l(c2, c3);
                } else if (slice == 1) {
                    *(float2*)(g_k + e0) = make_float2(c0, c1);
                    *(float2*)(g_k + e1) = make_float2(c2, c3);
                    *(uint32_t*)(g_kbh + e0) = pack2h(c0, c1);
                    *(uint32_t*)(g_kbl + e0) = pack2l(c0, c1);
                    *(uint32_t*)(g_kbh + e1) = pack2h(c2, c3);
                    *(uint32_t*)(g_kbl + e1) = pack2l(c2, c3);
                } else {
                    *(float2*)(g_v + e0) = make_float2(c0, c1);
                    *(float2*)(g_v + e1) = make_float2(c2, c3);
                    *(uint32_t*)(g_vbh + e0) = pack2h(c0, c1);
                    *(uint32_t*)(g_vbl + e0) = pack2l(c0, c1);
                    *(uint32_t*)(g_vbh + e1) = pack2h(c2, c3);
                    *(uint32_t*)(g_vbl + e1) = pack2l(c2, c3);
                }
            } else {
                float2 bv = *(const float2*)(bias + gn);
                *(float2*)(C + (size_t)gm * 1024 + gn) =
                    make_float2(acc[i][j][0] + bv.x, acc[i][j][1] + bv.y);
                *(float2*)(C + (size_t)(gm + 8) * 1024 + gn) =
                    make_float2(acc[i][j][2] + bv.x, acc[i][j][3] + bv.y);
            }
        }
    }
}

// ---------------------------------------------------------------------------
// Sinkhorn sorting matrix (reads fp32 g_k)
// ---------------------------------------------------------------------------
__global__ __launch_bounds__(256)
void sinkhorn_k(const float* __restrict__ sort_w, const float* __restrict__ noise_u)
{
    __shared__ float sh[8192];
    const int bh = blockIdx.x, h = bh & 7, tid = threadIdx.x;
#pragma unroll 1
    for (int c = 0; c < 32; c++) {
        int idx = tid + c * 256;
        int uu = idx >> 7, dd = idx & 127;
        const float* kp = g_k + ((size_t)bh * 4096 + uu * 64) * 128 + dd;
        float s = 0.f;
#pragma unroll 8
        for (int i = 0; i < 64; i++) s += kp[(size_t)i * 128];
        sh[idx] = s;
    }
    __syncthreads();
    float logit[16];
#pragma unroll 1
    for (int c = 0; c < 16; c++) {
        int idx = tid + c * 256;
        int uu = idx >> 6, vv = idx & 63;
        const float* wp = sort_w + h * 8192 + vv;
        const float* bp = sh + uu * 128;
        float s = 0.f;
#pragma unroll 8
        for (int d = 0; d < 128; d++) s += bp[d] * wp[d * 64];
        float nu = noise_u[(size_t)bh * 4096 + idx];
        float g = -logf(-logf(nu + 1e-4f) + 1e-4f);
        logit[c] = (logf(fmaxf(s, 0.f) + 1e-6f) + g) * (1.0f / 0.75f);
    }
    __syncthreads();
#pragma unroll
    for (int c = 0; c < 16; c++) sh[tid + c * 256] = logit[c];
    __syncthreads();
    for (int it = 0; it < 5; it++) {
        if (tid < 64) {
            float m = -1e30f;
            for (int v = 0; v < 64; v++) m = fmaxf(m, sh[tid * 64 + ((v + tid) & 63)]);
            float s = 0.f;
            for (int v = 0; v < 64; v++) s += expf(sh[tid * 64 + ((v + tid) & 63)] - m);
            float l = m + logf(s);
            for (int v = 0; v < 64; v++) sh[tid * 64 + ((v + tid) & 63)] -= l;
        }
        __syncthreads();
        if (tid < 64) {
            float m = -1e30f;
            for (int u = 0; u < 64; u++) m = fmaxf(m, sh[u * 64 + tid]);
            float s = 0.f;
            for (int u = 0; u < 64; u++) s += expf(sh[u * 64 + tid] - m);
            float l = m + logf(s);
            for (int u = 0; u < 64; u++) sh[u * 64 + tid] -= l;
        }
        __syncthreads();
    }
#pragma unroll
    for (int c = 0; c < 16; c++) {
        int idx = tid + c * 256;
        int uu = idx >> 6, vv = idx & 63;
        g_R[(size_t)bh * 4096 + idx] = (vv < uu) ? expf(sh[idx]) : 0.f;
    }
}

// ---------------------------------------------------------------------------
// k_re/v_re soft permute, u-tiled, QUARTER-bucket per CTA (64-reg acc ->
// 2 CTAs/SM). grid: (8, 8, 32) = (arr*4+qtr, utile, bh). Outputs bf16 hi/lo.
// ---------------------------------------------------------------------------
__global__ __launch_bounds__(256)
void permute_tiled_k(void)
{
    const int arr = blockIdx.x >> 2, qtr = blockIdx.x & 3;
    const int u0 = blockIdx.y * 8, bh = blockIdx.z;
    const int tid = threadIdx.x;

    __shared__ float rr[512];
    for (int i = tid; i < 512; i += 256)
        rr[i] = g_R[(size_t)bh * 4096 + (u0 + (i >> 6)) * 64 + (i & 63)];
    __syncthreads();

    const float4* src = (const float4*)(arr == 0 ? g_k : g_v) + (size_t)bh * 131072 + qtr * 512 + tid;
    const size_t dbase = (size_t)(bh * 64 + u0) * 2048 + qtr * 512 + tid;

    float4 acc[8][2];
#pragma unroll
    for (int t = 0; t < 8; t++)
#pragma unroll
        for (int j = 0; j < 2; j++) acc[t][j] = make_float4(0.f, 0.f, 0.f, 0.f);

    const int vmax = u0 + 7;
#pragma unroll 1
    for (int vv = 0; vv < vmax; vv++) {
        float4 d[2];
#pragma unroll
        for (int j = 0; j < 2; j++) d[j] = src[(size_t)vv * 2048 + j * 256];
#pragma unroll
        for (int t = 0; t < 8; t++) {
            float r = rr[t * 64 + vv];
#pragma unroll
            for (int j = 0; j < 2; j++) {
                acc[t][j].x += r * d[j].x; acc[t][j].y += r * d[j].y;
                acc[t][j].z += r * d[j].z; acc[t][j].w += r * d[j].w;
            }
        }
    }
    uint2* dh = (uint2*)(arr == 0 ? g_krh : g_vrh) + dbase;
    uint2* dl = (uint2*)(arr == 0 ? g_krl : g_vrl) + dbase;
#pragma unroll
    for (int t = 0; t < 8; t++)
#pragma unroll
        for (int j = 0; j < 2; j++) {
            float4 a = acc[t][j];
            dh[(size_t)t * 2048 + j * 256] = make_uint2(pack2h(a.x, a.y), pack2h(a.z, a.w));
            dl[(size_t)t * 2048 + j * 256] = make_uint2(pack2l(a.x, a.y), pack2l(a.z, a.w));
        }
}

// ---------------------------------------------------------------------------
// Bucketed attention: bf16x3 tensor dots AND out phases. smem = 104448 B.
// ---------------------------------------------------------------------------
#define OFF_QH   0
#define OFF_QL   17408
#define OFF_K2H  34816
#define OFF_K2L  69632
#define OFF_SD   69632
#define OFF_PH   0
#define OFF_PL   17408
#define OFF_V2H  34816
#define OFF_V2L  69632
#define ATTN_SMEM 104448

__global__ __launch_bounds__(256)
void attn_k(void)
{
    extern __shared__ float smf[];
    char* smc = (char*)smf;
    const uint32_t sb = smem_u32(smf);
    float* sd = smf + OFF_SD / 4;
    const int u = blockIdx.x, bh = blockIdx.y, tid = threadIdx.x;
    const int lane = tid & 31, wid = tid >> 5;
    const int wm = wid >> 2, wn = wid & 3;
    const size_t boff = ((size_t)bh * 4096 + u * 64) * 128;
    const size_t reoff = ((size_t)bh * 64 + u) * 8192;

    {
        const uint4* qh = (const uint4*)g_qbh + (boff >> 3);
        const uint4* ql = (const uint4*)g_qbl + (boff >> 3);
#pragma unroll
        for (int c = 0; c < 4; c++) {
            int idx = tid + c * 256;
            uint32_t so = (idx >> 4) * 272 + (idx & 15) * 16;
            *(uint4*)(smc + OFF_QH + so) = qh[idx];
            *(uint4*)(smc + OFF_QL + so) = ql[idx];
        }
        const uint4* krh = (const uint4*)g_krh + (reoff >> 3);
        const uint4* krl = (const uint4*)g_krl + (reoff >> 3);
        const uint4* kbh = (const uint4*)g_kbh + (boff >> 3);
        const uint4* kbl = (const uint4*)g_kbl + (boff >> 3);
#pragma unroll
        for (int c = 0; c < 8; c++) {
            int idx = tid + c * 256;
            int r = idx >> 4;
            uint32_t so = r * 272 + (idx & 15) * 16;
            *(uint4*)(smc + OFF_K2H + so) = (r < 64) ? krh[idx] : kbh[idx - 1024];
            *(uint4*)(smc + OFF_K2L + so) = (r < 64) ? krl[idx] : kbl[idx - 1024];
        }
    }
    __syncthreads();

    {
        const int arow = (lane & 7) + ((lane >> 3) & 1) * 8;
        const int acol = ((lane >> 4) & 1) * 8;
        const int brow = (lane & 7) + ((lane >> 4) & 1) * 8;
        const int bcol = ((lane >> 3) & 1) * 8;
        float acc[2][4][4];
#pragma unroll
        for (int i = 0; i < 2; i++)
#pragma unroll
            for (int j = 0; j < 4; j++)
#pragma unroll
                for (int r = 0; r < 4; r++) acc[i][j][r] = 0.f;

#pragma unroll
        for (int kc = 0; kc < 8; kc++) {
            uint32_t bh[4][2], bl[4][2];
#pragma unroll
            for (int jj = 0; jj < 2; jj++) {
                uint32_t ba = sb + OFF_K2H + ((wn * 32 + jj * 16 + brow) * 136 + kc * 16 + bcol) * 2;
                uint32_t rb[4];
                ldsm4(rb, ba);
                bh[jj * 2][0] = rb[0]; bh[jj * 2][1] = rb[1];
                bh[jj * 2 + 1][0] = rb[2]; bh[jj * 2 + 1][1] = rb[3];
                ldsm4(rb, ba + (OFF_K2L - OFF_K2H));
                bl[jj * 2][0] = rb[0]; bl[jj * 2][1] = rb[1];
                bl[jj * 2 + 1][0] = rb[2]; bl[jj * 2 + 1][1] = rb[3];
            }
#pragma unroll
            for (int i = 0; i < 2; i++) {
                uint32_t aa = sb + OFF_QH + ((wm * 32 + i * 16 + arow) * 136 + kc * 16 + acol) * 2;
                uint32_t ah[4], al[4];
                ldsm4(ah, aa);
                ldsm4(al, aa + (OFF_QL - OFF_QH));
#pragma unroll
                for (int j = 0; j < 4; j++) mma16816(acc[i][j], ah, bh[j]);
#pragma unroll
                for (int j = 0; j < 4; j++) mma16816(acc[i][j], ah, bl[j]);
#pragma unroll
                for (int j = 0; j < 4; j++) mma16816(acc[i][j], al, bh[j]);
            }
        }
        __syncthreads();
        const float sc = 0.03125f;
#pragma unroll
        for (int i = 0; i < 2; i++)
#pragma unroll
            for (int j = 0; j < 4; j++) {
                int row = wm * 32 + i * 16 + (lane >> 2);
                int col = wn * 32 + j * 8 + (lane & 3) * 2;
                *(float2*)&sd[row * 130 + col] = make_float2(acc[i][j][0] * sc, acc[i][j][1] * sc);
                *(float2*)&sd[(row + 8) * 130 + col] = make_float2(acc[i][j][2] * sc, acc[i][j][3] * sc);
            }
    }
    __syncthreads();

    {
        const int row = tid >> 2;
        float* rp = sd + row * 130 + (tid & 3) * 32;
        float m = -1e30f;
#pragma unroll
        for (int j = 0; j < 32; j++) m = fmaxf(m, rp[(j + tid) & 31]);
        m = fmaxf(m, __shfl_xor_sync(0xffffffffu, m, 1, 4));
        m = fmaxf(m, __shfl_xor_sync(0xffffffffu, m, 2, 4));
        float s = 0.f;
#pragma unroll
        for (int j = 0; j < 32; j++) {
            int jj = (j + tid) & 31;
            float e = __expf(rp[jj] - m);
            rp[jj] = e;
            s += e;
        }
        s += __shfl_xor_sync(0xffffffffu, s, 1, 4);
        s += __shfl_xor_sync(0xffffffffu, s, 2, 4);
        float inv = 1.f / s;
#pragma unroll
        for (int j = 0; j < 32; j++) { int jj = (j + tid) & 31; rp[jj] *= inv; }

        const uint4* vrh = (const uint4*)g_vrh + (reoff >> 3);
        const uint4* vbh = (const uint4*)g_vbh + (boff >> 3);
#pragma unroll
        for (int c = 0; c < 8; c++) {
            int idx = tid + c * 256;
            int r = idx >> 4;
            uint32_t so = r * 272 + (idx & 15) * 16;
            *(uint4*)(smc + OFF_V2H + so) = (r < 64) ? vrh[idx] : vbh[idx - 1024];
        }
    }
    __syncthreads();

    {
        const int row = tid >> 2, c0 = (tid & 3) * 32;
        const float* rp = sd + row * 130 + c0;
        uint32_t* ph = (uint32_t*)(smc + OFF_PH + (row * 136 + c0) * 2);
        uint32_t* pl = (uint32_t*)(smc + OFF_PL + (row * 136 + c0) * 2);
#pragma unroll
        for (int j = 0; j < 16; j++) {
            float a = rp[j * 2], b = rp[j * 2 + 1];
            ph[j] = pack2h(a, b);
            pl[j] = pack2l(a, b);
        }
    }
    __syncthreads();

    {
        const uint4* vrl = (const uint4*)g_vrl + (reoff >> 3);
        const uint4* vbl = (const uint4*)g_vbl + (boff >> 3);
#pragma unroll
        for (int c = 0; c < 8; c++) {
            int idx = tid + c * 256;
            int r = idx >> 4;
            uint32_t so = r * 272 + (idx & 15) * 16;
            *(uint4*)(smc + OFF_V2L + so) = (r < 64) ? vrl[idx] : vbl[idx - 1024];
        }
    }
    __syncthreads();

    {
        const int arow = (lane & 7) + ((lane >> 3) & 1) * 8;
        const int acol = ((lane >> 4) & 1) * 8;
        const int trow = (lane & 7) + ((lane >> 3) & 1) * 8;
        const int tcol = ((lane >> 4) & 1) * 8;
        float acc[2][4][4];
#pragma unroll
        for (int i = 0; i < 2; i++)
#pragma unroll
            for (int j = 0; j < 4; j++)
#pragma unroll
                for (int r = 0; r < 4; r++) acc[i][j][r] = 0.f;

#pragma unroll
        for (int kc = 0; kc < 8; kc++) {
            uint32_t bh[4][2], bl[4][2];
#pragma unroll
            for (int jo = 0; jo < 2; jo++) {
                uint32_t ba = sb + OFF_V2H + ((kc * 16 + trow) * 136 + wn * 32 + jo * 16 + tcol) * 2;
                uint32_t rb[4];
                ldsm4t(rb, ba);
                bh[jo * 2][0] = rb[0]; bh[jo * 2][1] = rb[1];
                bh[jo * 2 + 1][0] = rb[2]; bh[jo * 2 + 1][1] = rb[3];
                ldsm4t(rb, ba + (OFF_V2L - OFF_V2H));
                bl[jo * 2][0] = rb[0]; bl[jo * 2][1] = rb[1];
                bl[jo * 2 + 1][0] = rb[2]; bl[jo * 2 + 1][1] = rb[3];
            }
#pragma unroll
            for (int i = 0; i < 2; i++) {
                uint32_t aa = sb + OFF_PH + ((wm * 32 + i * 16 + arow) * 136 + kc * 16 + acol) * 2;
                uint32_t ah[4], al[4];
                ldsm4(ah, aa);
                ldsm4(al, aa + (OFF_PL - OFF_PH));
#pragma unroll
                for (int j = 0; j < 4; j++) mma16816(acc[i][j], ah, bh[j]);
#pragma unroll
                for (int j = 0; j < 4; j++) mma16816(acc[i][j], ah, bl[j]);
#pragma unroll
                for (int j = 0; j < 4; j++) mma16816(acc[i][j], al, bh[j]);
            }
        }

        const int bb = bh >> 3, hh = bh & 7;
#pragma unroll
        for (int i = 0; i < 2; i++)
#pragma unroll
            for (int j = 0; j < 4; j++) {
                int r0 = wm * 32 + i * 16 + (lane >> 2);
                int col = wn * 32 + j * 8 + (lane & 3) * 2;
                size_t b0 = (size_t)(bb * 4096 + u * 64 + r0) * 1024 + hh * 128 + col;
                size_t b1 = (size_t)(bb * 4096 + u * 64 + r0 + 8) * 1024 + hh * 128 + col;
                *(uint32_t*)(g_ah + b0) = pack2h(acc[i][j][0], acc[i][j][1]);
                *(uint32_t*)(g_al + b0) = pack2l(acc[i][j][0], acc[i][j][1]);
                *(uint32_t*)(g_ah + b1) = pack2h(acc[i][j][2], acc[i][j][3]);
                *(uint32_t*)(g_al + b1) = pack2l(acc[i][j][2], acc[i][j][3]);
            }
    }
}

// ---------------------------------------------------------------------------
extern "C" void kernel_launch(void* const* d_in, const int* in_sizes, int n_in,
                              void* d_out, int out_size)
{
    const float* x       = (const float*)d_in[0];
    const float* w_qkv   = (const float*)d_in[1];
    const float* sort_w  = (const float*)d_in[2];
    const float* w_out   = (const float*)d_in[3];
    const float* b_out   = (const float*)d_in[4];
    const float* noise_u = (const float*)d_in[5];
    float* out = (float*)d_out;

    __nv_bfloat16 *xh, *xl, *wqh, *wql, *woh, *wol, *ah, *al;
    cudaGetSymbolAddress((void**)&xh,  g_xh);  cudaGetSymbolAddress((void**)&xl,  g_xl);
    cudaGetSymbolAddress((void**)&wqh, g_wqh); cudaGetSymbolAddress((void**)&wql, g_wql);
    cudaGetSymbolAddress((void**)&woh, g_woh); cudaGetSymbolAddress((void**)&wol, g_wol);
    cudaGetSymbolAddress((void**)&ah,  g_ah);  cudaGetSymbolAddress((void**)&al,  g_al);

    (void)cudaFuncSetAttribute(attn_k, cudaFuncAttributeMaxDynamicSharedMemorySize, ATTN_SMEM);
    (void)cudaFuncSetAttribute(mma_gemm<0>, cudaFuncAttributeMaxDynamicSharedMemorySize, 81920);
    (void)cudaFuncSetAttribute(mma_gemm<1>, cudaFuncAttributeMaxDynamicSharedMemorySize, 81920);

    // prepass: fused bf16 hi/lo splits
    split_all_k<<<20480, 256>>>((const float4*)x, (const float4*)w_qkv, (const float4*)w_out);

    // 1) qkv = x @ w_qkv^T  (tensor bf16x3)
    mma_gemm<0><<<dim3(24, 128), 256, 81920>>>(xh, xl, wqh, wql, nullptr, nullptr);
    // 2) sinkhorn R
    sinkhorn_k<<<32, 256>>>(sort_w, noise_u);
    // 3) k_re / v_re (bf16 splits), u-tiled quarter-bucket
    permute_tiled_k<<<dim3(8, 8, 32), 256>>>();
    // 4) bucketed attention (tensor dots + tensor out) -> g_ah/g_al
    attn_k<<<dim3(64, 32), 256, ATTN_SMEM>>>();
    // 5) out = attn @ w_out^T + b_out  (tensor bf16x3)
    mma_gemm<1><<<dim3(8, 128), 256, 81920>>>(ah, al, woh, wol, out, b_out);
}